// round 3
// baseline (speedup 1.0000x reference)
#include <cuda_runtime.h>
#include <math.h>

#define BB 8
#define CIN 512
#define NPIX 4096
#define CKD 64
#define COUT 128
#define HP 66
#define PLANE (HP*HP)   /* 4356 */
#define KCONV 4608      /* 512*9 */

typedef unsigned long long ull;

// packed f32x2 FMA: d = a*b + c on both 32-bit lanes (Blackwell FFMA2)
__device__ __forceinline__ ull ffma2(ull a, ull b, ull c) {
    ull d;
    asm("fma.rn.f32x2 %0, %1, %2, %3;" : "=l"(d) : "l"(a), "l"(b), "l"(c));
    return d;
}
__device__ __forceinline__ ull dup2(float v) {
    unsigned u = __float_as_uint(v);
    return (ull)u | ((ull)u << 32);
}
__device__ __forceinline__ float lo2(ull a) { return __uint_as_float((unsigned)a); }
__device__ __forceinline__ float hi2(ull a) { return __uint_as_float((unsigned)(a >> 32)); }

// ---------------- scratch (device globals; no allocation) ----------------
__device__ float g_Q[BB*CKD*NPIX];                 // [b][k][n] normalized q
__device__ float g_K[BB*CKD*NPIX];                 // [b][k][n] normalized k
__device__ float g_V[(size_t)BB*CIN*NPIX];         // [b][c][n] relu(v)
__device__ float g_simP[BB*8*CIN*CKD];             // split-K partials
__device__ float g_simT[BB*CIN*CKD];               // [b][c][k]
__device__ float g_Wos[BB*CIN*CKD];                // [b][o][k] = Wo @ simT
__device__ float g_fusep[(size_t)BB*CIN*PLANE];    // zero-padded fuse [b][c][66][66]

// ================= K1: QK GEMM + per-pixel L2 normalization =================
__global__ __launch_bounds__(256) void qk_kernel(
    const float* __restrict__ x,
    const float* __restrict__ wq, const float* __restrict__ sq, const float* __restrict__ bq,
    const float* __restrict__ wk, const float* __restrict__ sk, const float* __restrict__ bk)
{
    __shared__ __align__(16) float As[16][128];
    __shared__ __align__(16) ull   Bs2[16][4][16];
    __shared__ float Cs[128][64];
    const int b = blockIdx.y;
    const int col0 = blockIdx.x * 64;
    const float* X = x + (size_t)b * CIN * NPIX;
    const int t = threadIdx.x;
    const int tr = t >> 4, tc = t & 15;
    ull acc2[4][4];
    #pragma unroll
    for (int i = 0; i < 4; i++)
        #pragma unroll
        for (int j = 0; j < 4; j++) acc2[i][j] = 0ull;

    for (int kb = 0; kb < CIN; kb += 16) {
        #pragma unroll
        for (int q = 0; q < 2; q++) {
            int idx = t * 2 + q;
            int row = idx >> 2;
            int k4  = (idx & 3) << 2;
            const float* ar = (row < 64) ? (wq + row * CIN) : (wk + (row - 64) * CIN);
            float4 v4 = *reinterpret_cast<const float4*>(ar + kb + k4);
            As[k4+0][row] = v4.x; As[k4+1][row] = v4.y;
            As[k4+2][row] = v4.z; As[k4+3][row] = v4.w;
        }
        {
            int kk = t >> 4;
            int tcw = t & 15;
            float4 v4 = *reinterpret_cast<const float4*>(X + (size_t)(kb + kk) * NPIX + col0 + tcw*4);
            Bs2[kk][0][tcw] = dup2(v4.x); Bs2[kk][1][tcw] = dup2(v4.y);
            Bs2[kk][2][tcw] = dup2(v4.z); Bs2[kk][3][tcw] = dup2(v4.w);
        }
        __syncthreads();
        #pragma unroll
        for (int kk = 0; kk < 16; kk++) {
            ulonglong2 a01 = *reinterpret_cast<ulonglong2*>(&As[kk][tr*8]);
            ulonglong2 a23 = *reinterpret_cast<ulonglong2*>(&As[kk][tr*8+4]);
            ull av2[4] = {a01.x, a01.y, a23.x, a23.y};
            ull bv2[4] = {Bs2[kk][0][tc], Bs2[kk][1][tc], Bs2[kk][2][tc], Bs2[kk][3][tc]};
            #pragma unroll
            for (int i = 0; i < 4; i++)
                #pragma unroll
                for (int j = 0; j < 4; j++)
                    acc2[i][j] = ffma2(av2[i], bv2[j], acc2[i][j]);
        }
        __syncthreads();
    }
    #pragma unroll
    for (int i2 = 0; i2 < 4; i2++) {
        int rlo = tr * 8 + 2*i2, rhi = rlo + 1;
        float slo, blo, shi, bhi;
        if (rlo < 64) { slo = sq[rlo]; blo = bq[rlo]; } else { slo = sk[rlo-64]; blo = bk[rlo-64]; }
        if (rhi < 64) { shi = sq[rhi]; bhi = bq[rhi]; } else { shi = sk[rhi-64]; bhi = bk[rhi-64]; }
        #pragma unroll
        for (int j = 0; j < 4; j++) {
            Cs[rlo][tc*4 + j] = fmaf(lo2(acc2[i2][j]), slo, blo);
            Cs[rhi][tc*4 + j] = fmaf(hi2(acc2[i2][j]), shi, bhi);
        }
    }
    __syncthreads();
    if (t < 128) {
        int col  = t & 63;
        int half = t >> 6;
        float ssum = 0.f;
        #pragma unroll 8
        for (int r = 0; r < 64; r++) {
            float v = Cs[half*64 + r][col];
            ssum = fmaf(v, v, ssum);
        }
        float inv = 1.f / fmaxf(sqrtf(ssum), 1e-12f);
        float* dst = (half == 0 ? g_Q : g_K) + (size_t)b * CKD * NPIX + col0 + col;
        for (int r = 0; r < 64; r++)
            dst[(size_t)r * NPIX] = Cs[half*64 + r][col] * inv;
    }
}

// ================= K2: V = relu(affine(Wv @ X)) =================
__global__ __launch_bounds__(256) void v_kernel(
    const float* __restrict__ x, const float* __restrict__ wv,
    const float* __restrict__ sv, const float* __restrict__ bv)
{
    __shared__ __align__(16) float As[16][128];
    __shared__ __align__(16) ull   Bs2[16][4][16];
    const int b = blockIdx.z;
    const int row0 = blockIdx.y * 128;
    const int col0 = blockIdx.x * 64;
    const float* X = x + (size_t)b * CIN * NPIX;
    const int t = threadIdx.x;
    const int tr = t >> 4, tc = t & 15;
    ull acc2[4][4];
    #pragma unroll
    for (int i = 0; i < 4; i++)
        #pragma unroll
        for (int j = 0; j < 4; j++) acc2[i][j] = 0ull;

    for (int kb = 0; kb < CIN; kb += 16) {
        #pragma unroll
        for (int q = 0; q < 2; q++) {
            int idx = t * 2 + q;
            int row = idx >> 2;
            int k4  = (idx & 3) << 2;
            float4 v4 = *reinterpret_cast<const float4*>(wv + (size_t)(row0 + row) * CIN + kb + k4);
            As[k4+0][row] = v4.x; As[k4+1][row] = v4.y;
            As[k4+2][row] = v4.z; As[k4+3][row] = v4.w;
        }
        {
            int kk = t >> 4;
            int tcw = t & 15;
            float4 v4 = *reinterpret_cast<const float4*>(X + (size_t)(kb + kk) * NPIX + col0 + tcw*4);
            Bs2[kk][0][tcw] = dup2(v4.x); Bs2[kk][1][tcw] = dup2(v4.y);
            Bs2[kk][2][tcw] = dup2(v4.z); Bs2[kk][3][tcw] = dup2(v4.w);
        }
        __syncthreads();
        #pragma unroll
        for (int kk = 0; kk < 16; kk++) {
            ulonglong2 a01 = *reinterpret_cast<ulonglong2*>(&As[kk][tr*8]);
            ulonglong2 a23 = *reinterpret_cast<ulonglong2*>(&As[kk][tr*8+4]);
            ull av2[4] = {a01.x, a01.y, a23.x, a23.y};
            ull bv2[4] = {Bs2[kk][0][tc], Bs2[kk][1][tc], Bs2[kk][2][tc], Bs2[kk][3][tc]};
            #pragma unroll
            for (int i = 0; i < 4; i++)
                #pragma unroll
                for (int j = 0; j < 4; j++)
                    acc2[i][j] = ffma2(av2[i], bv2[j], acc2[i][j]);
        }
        __syncthreads();
    }
    #pragma unroll
    for (int i2 = 0; i2 < 4; i2++) {
        int rlo = row0 + tr * 8 + 2*i2;
        float s0 = sv[rlo],   b0 = bv[rlo];
        float s1 = sv[rlo+1], b1 = bv[rlo+1];
        float4 o0, o1;
        o0.x = fmaxf(fmaf(lo2(acc2[i2][0]), s0, b0), 0.f);
        o0.y = fmaxf(fmaf(lo2(acc2[i2][1]), s0, b0), 0.f);
        o0.z = fmaxf(fmaf(lo2(acc2[i2][2]), s0, b0), 0.f);
        o0.w = fmaxf(fmaf(lo2(acc2[i2][3]), s0, b0), 0.f);
        o1.x = fmaxf(fmaf(hi2(acc2[i2][0]), s1, b1), 0.f);
        o1.y = fmaxf(fmaf(hi2(acc2[i2][1]), s1, b1), 0.f);
        o1.z = fmaxf(fmaf(hi2(acc2[i2][2]), s1, b1), 0.f);
        o1.w = fmaxf(fmaf(hi2(acc2[i2][3]), s1, b1), 0.f);
        *reinterpret_cast<float4*>(g_V + (size_t)b * CIN * NPIX + (size_t)rlo     * NPIX + col0 + tc*4) = o0;
        *reinterpret_cast<float4*>(g_V + (size_t)b * CIN * NPIX + (size_t)(rlo+1) * NPIX + col0 + tc*4) = o1;
    }
}

// ================= K3: simT partials: V[b] @ K[b]^T (split over n) =================
__global__ __launch_bounds__(256) void sim_kernel()
{
    __shared__ __align__(16) float As[16][64];  // [n][c]
    __shared__ __align__(16) ull   Bs2[16][4][16];
    const int b = blockIdx.z, chunk = blockIdx.y;
    const int row0 = blockIdx.x * 64;
    const float* V  = g_V + (size_t)b * CIN * NPIX;
    const float* Km = g_K + (size_t)b * CKD * NPIX;
    const int t = threadIdx.x;
    const int tr = t >> 4, tc = t & 15;
    ull acc2[2][4];
    #pragma unroll
    for (int i = 0; i < 2; i++)
        #pragma unroll
        for (int j = 0; j < 4; j++) acc2[i][j] = 0ull;

    const int nb0 = chunk * 512;
    for (int nb = nb0; nb < nb0 + 512; nb += 16) {
        {
            int r  = t >> 2;          // 0..63
            int n4 = (t & 3) << 2;
            float4 va = *reinterpret_cast<const float4*>(V  + (size_t)(row0 + r) * NPIX + nb + n4);
            As[n4+0][r] = va.x; As[n4+1][r] = va.y; As[n4+2][r] = va.z; As[n4+3][r] = va.w;
            float4 vb = *reinterpret_cast<const float4*>(Km + (size_t)r * NPIX + nb + n4);
            int jj = r & 3, cc = r >> 2;
            Bs2[n4+0][jj][cc] = dup2(vb.x);
            Bs2[n4+1][jj][cc] = dup2(vb.y);
            Bs2[n4+2][jj][cc] = dup2(vb.z);
            Bs2[n4+3][jj][cc] = dup2(vb.w);
        }
        __syncthreads();
        #pragma unroll
        for (int nn = 0; nn < 16; nn++) {
            ulonglong2 a01 = *reinterpret_cast<ulonglong2*>(&As[nn][tr*4]);
            ull av2[2] = {a01.x, a01.y};
            ull bv2[4] = {Bs2[nn][0][tc], Bs2[nn][1][tc], Bs2[nn][2][tc], Bs2[nn][3][tc]};
            #pragma unroll
            for (int i = 0; i < 2; i++)
                #pragma unroll
                for (int j = 0; j < 4; j++)
                    acc2[i][j] = ffma2(av2[i], bv2[j], acc2[i][j]);
        }
        __syncthreads();
    }
    #pragma unroll
    for (int i2 = 0; i2 < 2; i2++) {
        int clo = row0 + tr * 4 + 2*i2;
        float4 o0 = make_float4(lo2(acc2[i2][0]), lo2(acc2[i2][1]), lo2(acc2[i2][2]), lo2(acc2[i2][3]));
        float4 o1 = make_float4(hi2(acc2[i2][0]), hi2(acc2[i2][1]), hi2(acc2[i2][2]), hi2(acc2[i2][3]));
        *reinterpret_cast<float4*>(g_simP + ((size_t)(b*8 + chunk) * CIN + clo)     * CKD + tc*4) = o0;
        *reinterpret_cast<float4*>(g_simP + ((size_t)(b*8 + chunk) * CIN + clo + 1) * CKD + tc*4) = o1;
    }
}

// ================= K3b: deterministic split-K reduce =================
__global__ __launch_bounds__(256) void sim_reduce()
{
    int idx = blockIdx.x * 256 + threadIdx.x;
    if (idx >= BB * CIN * CKD) return;
    int b = idx / (CIN * CKD);
    int rem = idx - b * CIN * CKD;
    float s = 0.f;
    #pragma unroll
    for (int p = 0; p < 8; p++)
        s += g_simP[(size_t)(b*8 + p) * CIN * CKD + rem];
    g_simT[idx] = s;
}

// ================= K4: Wos[b] = Wo @ simT[b]  (512x64, K=512) =================
__global__ __launch_bounds__(256) void wos_kernel(const float* __restrict__ wo)
{
    __shared__ __align__(16) float As[16][64];
    __shared__ __align__(16) ull   Bs2[16][4][16];
    const int b = blockIdx.y;
    const int row0 = blockIdx.x * 64;
    const float* ST = g_simT + (size_t)b * CIN * CKD;
    const int t = threadIdx.x;
    const int tr = t >> 4, tc = t & 15;
    ull acc2[2][4];
    #pragma unroll
    for (int i = 0; i < 2; i++)
        #pragma unroll
        for (int j = 0; j < 4; j++) acc2[i][j] = 0ull;

    for (int kb = 0; kb < CIN; kb += 16) {
        {
            int r  = t >> 2;
            int k4 = (t & 3) << 2;
            float4 va = *reinterpret_cast<const float4*>(wo + (size_t)(row0 + r) * CIN + kb + k4);
            As[k4+0][r] = va.x; As[k4+1][r] = va.y; As[k4+2][r] = va.z; As[k4+3][r] = va.w;
            int kk = t >> 4;
            int tcw = t & 15;
            float4 vb = *reinterpret_cast<const float4*>(ST + (size_t)(kb + kk) * CKD + tcw*4);
            Bs2[kk][0][tcw] = dup2(vb.x); Bs2[kk][1][tcw] = dup2(vb.y);
            Bs2[kk][2][tcw] = dup2(vb.z); Bs2[kk][3][tcw] = dup2(vb.w);
        }
        __syncthreads();
        #pragma unroll
        for (int kk = 0; kk < 16; kk++) {
            ulonglong2 a01 = *reinterpret_cast<ulonglong2*>(&As[kk][tr*4]);
            ull av2[2] = {a01.x, a01.y};
            ull bv2[4] = {Bs2[kk][0][tc], Bs2[kk][1][tc], Bs2[kk][2][tc], Bs2[kk][3][tc]};
            #pragma unroll
            for (int i = 0; i < 2; i++)
                #pragma unroll
                for (int j = 0; j < 4; j++)
                    acc2[i][j] = ffma2(av2[i], bv2[j], acc2[i][j]);
        }
        __syncthreads();
    }
    #pragma unroll
    for (int i2 = 0; i2 < 2; i2++) {
        int olo = row0 + tr * 4 + 2*i2;
        float4 o0 = make_float4(lo2(acc2[i2][0]), lo2(acc2[i2][1]), lo2(acc2[i2][2]), lo2(acc2[i2][3]));
        float4 o1 = make_float4(hi2(acc2[i2][0]), hi2(acc2[i2][1]), hi2(acc2[i2][2]), hi2(acc2[i2][3]));
        *reinterpret_cast<float4*>(g_Wos + (size_t)b * CIN * CKD + (size_t)olo     * CKD + tc*4) = o0;
        *reinterpret_cast<float4*>(g_Wos + (size_t)b * CIN * CKD + (size_t)(olo+1) * CKD + tc*4) = o1;
    }
}

// ================= K0: zero the borders of the padded fuse buffer =================
__global__ __launch_bounds__(256) void zero_border()
{
    int idx = blockIdx.x * 256 + threadIdx.x;
    if (idx >= BB * CIN * HP) return;
    int plane = idx / HP;
    int i = idx - plane * HP;
    float* p = g_fusep + (size_t)plane * PLANE;
    p[i] = 0.f;               // top row
    p[65*HP + i] = 0.f;       // bottom row
    p[i*HP] = 0.f;            // left col
    p[i*HP + 65] = 0.f;       // right col
}

// ================= K5: fuse = relu(affine(Wos @ Q)) + x + up -> padded layout ====
__global__ __launch_bounds__(256) void fuse_kernel(
    const float* __restrict__ x, const float* __restrict__ up,
    const float* __restrict__ so, const float* __restrict__ bo)
{
    __shared__ __align__(16) float As[16][128];
    __shared__ __align__(16) ull   Bs2[16][4][16];
    const int b = blockIdx.z;
    const int row0 = blockIdx.y * 128;
    const int h = blockIdx.x;
    const int col0 = h * 64;
    const float* Wos = g_Wos + (size_t)b * CIN * CKD;
    const float* Qm  = g_Q   + (size_t)b * CKD * NPIX;
    const int t = threadIdx.x;
    const int tr = t >> 4, tc = t & 15;
    ull acc2[4][4];
    #pragma unroll
    for (int i = 0; i < 4; i++)
        #pragma unroll
        for (int j = 0; j < 4; j++) acc2[i][j] = 0ull;

    for (int kb = 0; kb < CKD; kb += 16) {
        #pragma unroll
        for (int q = 0; q < 2; q++) {
            int idx = t * 2 + q;
            int row = idx >> 2;
            int k4  = (idx & 3) << 2;
            float4 v4 = *reinterpret_cast<const float4*>(Wos + (size_t)(row0 + row) * CKD + kb + k4);
            As[k4+0][row] = v4.x; As[k4+1][row] = v4.y;
            As[k4+2][row] = v4.z; As[k4+3][row] = v4.w;
        }
        {
            int kk = t >> 4;
            int tcw = t & 15;
            float4 v4 = *reinterpret_cast<const float4*>(Qm + (size_t)(kb + kk) * NPIX + col0 + tcw*4);
            Bs2[kk][0][tcw] = dup2(v4.x); Bs2[kk][1][tcw] = dup2(v4.y);
            Bs2[kk][2][tcw] = dup2(v4.z); Bs2[kk][3][tcw] = dup2(v4.w);
        }
        __syncthreads();
        #pragma unroll
        for (int kk = 0; kk < 16; kk++) {
            ulonglong2 a01 = *reinterpret_cast<ulonglong2*>(&As[kk][tr*8]);
            ulonglong2 a23 = *reinterpret_cast<ulonglong2*>(&As[kk][tr*8+4]);
            ull av2[4] = {a01.x, a01.y, a23.x, a23.y};
            ull bv2[4] = {Bs2[kk][0][tc], Bs2[kk][1][tc], Bs2[kk][2][tc], Bs2[kk][3][tc]};
            #pragma unroll
            for (int i = 0; i < 4; i++)
                #pragma unroll
                for (int j = 0; j < 4; j++)
                    acc2[i][j] = ffma2(av2[i], bv2[j], acc2[i][j]);
        }
        __syncthreads();
    }
    #pragma unroll
    for (int i2 = 0; i2 < 4; i2++) {
        #pragma unroll
        for (int half = 0; half < 2; half++) {
            int row = row0 + tr * 8 + 2*i2 + half;
            float s = so[row], bi = bo[row];
            size_t xoff = (size_t)b * CIN * NPIX + (size_t)row * NPIX + col0 + tc*4;
            float4 xv = *reinterpret_cast<const float4*>(x + xoff);
            float4 uv = *reinterpret_cast<const float4*>(up + xoff);
            float* dst = g_fusep + ((size_t)b * CIN + row) * PLANE + (h + 1) * HP + 1 + tc*4;
            float a0 = half ? hi2(acc2[i2][0]) : lo2(acc2[i2][0]);
            float a1 = half ? hi2(acc2[i2][1]) : lo2(acc2[i2][1]);
            float a2 = half ? hi2(acc2[i2][2]) : lo2(acc2[i2][2]);
            float a3 = half ? hi2(acc2[i2][3]) : lo2(acc2[i2][3]);
            dst[0] = fmaxf(fmaf(a0, s, bi), 0.f) + xv.x + uv.x;
            dst[1] = fmaxf(fmaf(a1, s, bi), 0.f) + xv.y + uv.y;
            dst[2] = fmaxf(fmaf(a2, s, bi), 0.f) + xv.z + uv.z;
            dst[3] = fmaxf(fmaf(a3, s, bi), 0.f) + xv.w + uv.w;
        }
    }
}

// ================= K6: 3x3 conv as implicit GEMM [128,4608]@[4608,64] per row ====
__global__ __launch_bounds__(256) void conv_kernel(
    const float* __restrict__ wsm, const float* __restrict__ ssc,
    const float* __restrict__ bsc, float* __restrict__ out)
{
    __shared__ __align__(16) float As[16][128];
    __shared__ __align__(16) ull   Bs2[16][4][16];
    const int h = blockIdx.x, b = blockIdx.y;
    const int t = threadIdx.x;
    const int tr = t >> 4, tc = t & 15;
    ull acc2[4][4];
    #pragma unroll
    for (int i = 0; i < 4; i++)
        #pragma unroll
        for (int j = 0; j < 4; j++) acc2[i][j] = 0ull;

    const float* fbase = g_fusep + (size_t)b * CIN * PLANE;
    for (int kb = 0; kb < KCONV; kb += 16) {
        #pragma unroll
        for (int q = 0; q < 2; q++) {
            int idx = t * 2 + q;
            int row = idx >> 2;
            int k4  = (idx & 3) << 2;
            float4 v4 = *reinterpret_cast<const float4*>(wsm + (size_t)row * KCONV + kb + k4);
            As[k4+0][row] = v4.x; As[k4+1][row] = v4.y;
            As[k4+2][row] = v4.z; As[k4+3][row] = v4.w;
        }
        {
            int kk = t >> 4;
            int tcw = t & 15;
            int w0 = tcw << 2;
            int k  = kb + kk;
            int ic = k / 9;
            int r9 = k - ic * 9;
            int dy = r9 / 3;
            int dx = r9 - dy * 3;
            const float* src = fbase + (size_t)ic * PLANE + (h + dy) * HP + dx + w0;
            Bs2[kk][0][tcw] = dup2(src[0]);
            Bs2[kk][1][tcw] = dup2(src[1]);
            Bs2[kk][2][tcw] = dup2(src[2]);
            Bs2[kk][3][tcw] = dup2(src[3]);
        }
        __syncthreads();
        #pragma unroll
        for (int kk = 0; kk < 16; kk++) {
            ulonglong2 a01 = *reinterpret_cast<ulonglong2*>(&As[kk][tr*8]);
            ulonglong2 a23 = *reinterpret_cast<ulonglong2*>(&As[kk][tr*8+4]);
            ull av2[4] = {a01.x, a01.y, a23.x, a23.y};
            ull bv2[4] = {Bs2[kk][0][tc], Bs2[kk][1][tc], Bs2[kk][2][tc], Bs2[kk][3][tc]};
            #pragma unroll
            for (int i = 0; i < 4; i++)
                #pragma unroll
                for (int j = 0; j < 4; j++)
                    acc2[i][j] = ffma2(av2[i], bv2[j], acc2[i][j]);
        }
        __syncthreads();
    }
    #pragma unroll
    for (int i2 = 0; i2 < 4; i2++) {
        int oclo = tr * 8 + 2*i2;
        float s0 = ssc[oclo],   b0 = bsc[oclo];
        float s1 = ssc[oclo+1], b1 = bsc[oclo+1];
        float4 o0, o1;
        o0.x = fmaxf(fmaf(lo2(acc2[i2][0]), s0, b0), 0.f);
        o0.y = fmaxf(fmaf(lo2(acc2[i2][1]), s0, b0), 0.f);
        o0.z = fmaxf(fmaf(lo2(acc2[i2][2]), s0, b0), 0.f);
        o0.w = fmaxf(fmaf(lo2(acc2[i2][3]), s0, b0), 0.f);
        o1.x = fmaxf(fmaf(hi2(acc2[i2][0]), s1, b1), 0.f);
        o1.y = fmaxf(fmaf(hi2(acc2[i2][1]), s1, b1), 0.f);
        o1.z = fmaxf(fmaf(hi2(acc2[i2][2]), s1, b1), 0.f);
        o1.w = fmaxf(fmaf(hi2(acc2[i2][3]), s1, b1), 0.f);
        *reinterpret_cast<float4*>(out + ((size_t)(b * COUT + oclo))     * NPIX + h * 64 + tc*4) = o0;
        *reinterpret_cast<float4*>(out + ((size_t)(b * COUT + oclo + 1)) * NPIX + h * 64 + tc*4) = o1;
    }
}

// ================= launch =================
extern "C" void kernel_launch(void* const* d_in, const int* in_sizes, int n_in,
                              void* d_out, int out_size)
{
    const float* x  = (const float*)d_in[0];
    const float* up = (const float*)d_in[1];
    const float* wq = (const float*)d_in[2];
    const float* sq = (const float*)d_in[3];
    const float* bq = (const float*)d_in[4];
    const float* wk = (const float*)d_in[5];
    const float* sk = (const float*)d_in[6];
    const float* bk = (const float*)d_in[7];
    const float* wv = (const float*)d_in[8];
    const float* sv = (const float*)d_in[9];
    const float* bv = (const float*)d_in[10];
    const float* wo = (const float*)d_in[11];
    const float* so = (const float*)d_in[12];
    const float* bo = (const float*)d_in[13];
    const float* ws = (const float*)d_in[14];
    const float* ss = (const float*)d_in[15];
    const float* bs = (const float*)d_in[16];
    float* out = (float*)d_out;

    qk_kernel<<<dim3(64, 8), 256>>>(x, wq, sq, bq, wk, sk, bk);
    v_kernel<<<dim3(64, 4, 8), 256>>>(x, wv, sv, bv);
    sim_kernel<<<dim3(8, 8, 8), 256>>>();
    sim_reduce<<<(BB * CIN * CKD + 255) / 256, 256>>>();
    wos_kernel<<<dim3(8, 8), 256>>>(wo);
    zero_border<<<(BB * CIN * HP + 255) / 256, 256>>>();
    fuse_kernel<<<dim3(64, 4, 8), 256>>>(x, up, so, bo);
    conv_kernel<<<dim3(64, 8), 256>>>(ws, ss, bs, out);
}

// round 4
// speedup vs baseline: 2.5466x; 2.5466x over previous
#include <cuda_runtime.h>
#include <cuda_bf16.h>
#include <math.h>

#define BB 8
#define CIN 512
#define NPIX 4096
#define CKD 64
#define COUT 128
#define KCONV 4608

typedef __nv_bfloat16 bf16;

// ---------------- device scratch ----------------
__device__ __align__(16) bf16 g_XT[(size_t)BB*NPIX*1024];       // [b][n][hi512|lo512]
__device__ __align__(16) bf16 g_fuseT[(size_t)BB*66*66*1024];   // [b][y][x][hi512|lo512]
__device__ __align__(16) bf16 g_Wqk[128*1024];                  // rows: 64 q + 64 k
__device__ __align__(16) bf16 g_Wv[512*1024];
__device__ __align__(16) bf16 g_Wc[128*2*KCONV];                // permuted k'=(r9*512+ic)
__device__ float g_Q[BB*CKD*NPIX];                              // [b][ck][n]
__device__ float g_K[BB*CKD*NPIX];
__device__ float g_V[(size_t)BB*CIN*NPIX];
__device__ float g_simP[BB*8*CIN*CKD];
__device__ float g_simT[BB*CIN*CKD];
__device__ float g_Wos[BB*CIN*CKD];

// ---------------- helpers ----------------
__device__ __forceinline__ unsigned pk2(float a, float b) {
    __nv_bfloat162 h = __floats2bfloat162_rn(a, b);
    return *reinterpret_cast<unsigned*>(&h);
}
__device__ __forceinline__ float bhi_f(float x) { return __bfloat162float(__float2bfloat16_rn(x)); }
__device__ __forceinline__ void split8(const float* f, unsigned* hi, unsigned* lo) {
    #pragma unroll
    for (int i = 0; i < 4; i++) {
        float f0 = f[2*i], f1 = f[2*i+1];
        hi[i] = pk2(f0, f1);
        lo[i] = pk2(f0 - bhi_f(f0), f1 - bhi_f(f1));
    }
}
__device__ __forceinline__ void cpa16(void* sdst, const void* gsrc) {
    unsigned s = (unsigned)__cvta_generic_to_shared(sdst);
    asm volatile("cp.async.cg.shared.global [%0], [%1], 16;" :: "r"(s), "l"(gsrc));
}
__device__ __forceinline__ void cp_commit() { asm volatile("cp.async.commit_group;" ::: "memory"); }
__device__ __forceinline__ void cp_wait1()  { asm volatile("cp.async.wait_group 1;" ::: "memory"); }
__device__ __forceinline__ void cp_wait0()  { asm volatile("cp.async.wait_group 0;" ::: "memory"); }
__device__ __forceinline__ void mma16816(float* d, const unsigned* a, const unsigned* b) {
    asm("mma.sync.aligned.m16n8k16.row.col.f32.bf16.bf16.f32 "
        "{%0,%1,%2,%3},{%4,%5,%6,%7},{%8,%9},{%0,%1,%2,%3};"
        : "+f"(d[0]), "+f"(d[1]), "+f"(d[2]), "+f"(d[3])
        : "r"(a[0]), "r"(a[1]), "r"(a[2]), "r"(a[3]), "r"(b[0]), "r"(b[1]));
}

// ---------------- prep: split fp32 weights to hi/lo bf16 ----------------
__global__ __launch_bounds__(256) void prep_split(const float* __restrict__ src,
                                                  int rows, int which)
{
    bf16* dst = (which == 0) ? g_Wqk : (which == 1) ? (g_Wqk + 64*1024) : g_Wv;
    int idx = blockIdx.x * 256 + threadIdx.x;   // one per 8 elems
    if (idx >= rows * 64) return;
    int m = idx >> 6, kg = idx & 63;
    float f[8];
    *reinterpret_cast<float4*>(f)     = *reinterpret_cast<const float4*>(src + (size_t)m*512 + kg*8);
    *reinterpret_cast<float4*>(f + 4) = *reinterpret_cast<const float4*>(src + (size_t)m*512 + kg*8 + 4);
    unsigned hi[4], lo[4];
    split8(f, hi, lo);
    bf16* d = dst + (size_t)m * 1024 + kg*8;
    *reinterpret_cast<uint4*>(d)       = make_uint4(hi[0], hi[1], hi[2], hi[3]);
    *reinterpret_cast<uint4*>(d + 512) = make_uint4(lo[0], lo[1], lo[2], lo[3]);
}

// ---------------- prep: conv weights permute + split ----------------
__global__ __launch_bounds__(256) void prep_wconv(const float* __restrict__ ws)
{
    int idx = blockIdx.x * 256 + threadIdx.x;   // 128 * 576
    if (idx >= 128 * 576) return;
    int oc = idx / 576, kg = idx - oc * 576;
    int kp0 = kg * 8;
    int r9 = kp0 >> 9, ic = kp0 & 511;
    float f[8];
    #pragma unroll
    for (int j = 0; j < 8; j++)
        f[j] = ws[(size_t)oc * KCONV + (ic + j) * 9 + r9];
    unsigned hi[4], lo[4];
    split8(f, hi, lo);
    bf16* d = g_Wc + (size_t)oc * 2 * KCONV + kp0;
    *reinterpret_cast<uint4*>(d)         = make_uint4(hi[0], hi[1], hi[2], hi[3]);
    *reinterpret_cast<uint4*>(d + KCONV) = make_uint4(lo[0], lo[1], lo[2], lo[3]);
}

// ---------------- xt: x[b][c][n] -> XT[b][n][hi|lo] ----------------
__global__ __launch_bounds__(256) void xt_kernel(const float* __restrict__ x)
{
    __shared__ float tile[32][65];
    const int b = blockIdx.z, c0 = blockIdx.y * 32, n0 = blockIdx.x * 64;
    const int t = threadIdx.x;
    {
        int r = t >> 3, nq = (t & 7) * 8;
        const float* src = x + ((size_t)b * CIN + c0 + r) * NPIX + n0 + nq;
        float4 a = *reinterpret_cast<const float4*>(src);
        float4 c = *reinterpret_cast<const float4*>(src + 4);
        tile[r][nq+0]=a.x; tile[r][nq+1]=a.y; tile[r][nq+2]=a.z; tile[r][nq+3]=a.w;
        tile[r][nq+4]=c.x; tile[r][nq+5]=c.y; tile[r][nq+6]=c.z; tile[r][nq+7]=c.w;
    }
    __syncthreads();
    {
        int xc = t & 63, grp = t >> 6;
        float f[8];
        #pragma unroll
        for (int i = 0; i < 8; i++) f[i] = tile[grp*8 + i][xc];
        unsigned hi[4], lo[4];
        split8(f, hi, lo);
        bf16* d = g_XT + ((size_t)b * NPIX + n0 + xc) * 1024 + c0 + grp*8;
        *reinterpret_cast<uint4*>(d)       = make_uint4(hi[0], hi[1], hi[2], hi[3]);
        *reinterpret_cast<uint4*>(d + 512) = make_uint4(lo[0], lo[1], lo[2], lo[3]);
    }
}

// ---------------- mma fragment compute for one (A,B) term ----------------
__device__ __forceinline__ void mma_step(
    const bf16 (* __restrict__ A)[24], const bf16 (* __restrict__ B)[24],
    float acc[4][4][4], int wm, int wn, int lane)
{
    unsigned a[4][4], bb[4][2];
    const int qr = lane >> 2, qc = (lane & 3) * 2;
    #pragma unroll
    for (int mt = 0; mt < 4; mt++) {
        const bf16* p = &A[wm*64 + mt*16 + qr][qc];
        a[mt][0] = *(const unsigned*)p;
        a[mt][1] = *(const unsigned*)(p + 8*24);
        a[mt][2] = *(const unsigned*)(p + 8);
        a[mt][3] = *(const unsigned*)(p + 8*24 + 8);
    }
    #pragma unroll
    for (int nt = 0; nt < 4; nt++) {
        const bf16* p = &B[wn*32 + nt*8 + qr][qc];
        bb[nt][0] = *(const unsigned*)p;
        bb[nt][1] = *(const unsigned*)(p + 8);
    }
    #pragma unroll
    for (int mt = 0; mt < 4; mt++)
        #pragma unroll
        for (int nt = 0; nt < 4; nt++)
            mma16816(acc[mt][nt], a[mt], bb[nt]);
}

// ---------------- big GEMMs: MODE 0=qk, 1=v, 2=conv ----------------
template<int MODE>
__global__ __launch_bounds__(256, 1) void mma_gemm(
    const float* __restrict__ s0, const float* __restrict__ b0v,
    const float* __restrict__ s1, const float* __restrict__ b1v,
    float* __restrict__ outp)
{
    constexpr int KD = (MODE == 2) ? KCONV : 512;
    constexpr int NSTEP = KD / 16;
    __shared__ __align__(16) bf16 sA[2][2][128][24];
    __shared__ __align__(16) bf16 sB[2][2][128][24];
    const int bidx = blockIdx.z;
    const int n0 = blockIdx.x * 128;
    const int row0 = blockIdx.y * 128;
    const int t = threadIdx.x;
    const int lane = t & 31, w = t >> 5, wm = w >> 2, wn = w & 3;
    const int lrow = t >> 1, lhalf = t & 1;

    float acc[4][4][4];
    #pragma unroll
    for (int i = 0; i < 4; i++)
        #pragma unroll
        for (int j = 0; j < 4; j++)
            #pragma unroll
            for (int c = 0; c < 4; c++) acc[i][j][c] = 0.f;

    const bf16* W = (MODE == 0) ? g_Wqk : (MODE == 1) ? g_Wv : g_Wc;
    const bf16* aSrc  = W + (size_t)(row0 + lrow) * (2*KD) + lhalf*8;
    const bf16* bSrcX = g_XT + ((size_t)bidx * NPIX + n0 + lrow) * 1024 + lhalf*8;
    int yi = 0, xi = 0;
    if (MODE == 2) { yi = (n0 + lrow) >> 6; xi = (n0 + lrow) & 63; }

    auto load = [&](int st, int kc) {
        #pragma unroll
        for (int term = 0; term < 2; term++)
            cpa16(&sA[st][term][lrow][lhalf*8], aSrc + term*KD + kc);
        if (MODE == 2) {
            int r9 = kc >> 9, kin = kc & 511;
            int dy = r9 / 3, dx = r9 - dy*3;
            const bf16* bp = g_fuseT + (((size_t)bidx*66 + yi + dy)*66 + xi + dx)*1024 + kin + lhalf*8;
            cpa16(&sB[st][0][lrow][lhalf*8], bp);
            cpa16(&sB[st][1][lrow][lhalf*8], bp + 512);
        } else {
            #pragma unroll
            for (int term = 0; term < 2; term++)
                cpa16(&sB[st][term][lrow][lhalf*8], bSrcX + term*512 + kc);
        }
        cp_commit();
    };

    load(0, 0);
    #pragma unroll 1
    for (int kt = 0; kt < NSTEP; kt++) {
        int cur = kt & 1;
        if (kt + 1 < NSTEP) { load(cur ^ 1, (kt+1)*16); cp_wait1(); }
        else                 cp_wait0();
        __syncthreads();
        mma_step(sA[cur][0], sB[cur][0], acc, wm, wn, lane);   // hi*hi
        mma_step(sA[cur][0], sB[cur][1], acc, wm, wn, lane);   // hi*lo
        mma_step(sA[cur][1], sB[cur][0], acc, wm, wn, lane);   // lo*hi
        __syncthreads();
    }

    const int qr = lane >> 2, qc = (lane & 3) * 2;

    if (MODE == 0) {
        // affine
        #pragma unroll
        for (int mt = 0; mt < 4; mt++)
            #pragma unroll
            for (int h = 0; h < 2; h++) {
                int rowl = wm*64 + mt*16 + qr + 8*h;
                int ri = rowl & 63;
                float sc = wm ? s1[ri] : s0[ri];
                float bi = wm ? b1v[ri] : b0v[ri];
                #pragma unroll
                for (int nt = 0; nt < 4; nt++) {
                    acc[mt][nt][2*h]   = fmaf(acc[mt][nt][2*h],   sc, bi);
                    acc[mt][nt][2*h+1] = fmaf(acc[mt][nt][2*h+1], sc, bi);
                }
            }
        // per-pixel L2 norm over this warp's 64 rows (q rows for wm=0, k rows for wm=1)
        float inv[4][2];
        #pragma unroll
        for (int nt = 0; nt < 4; nt++)
            #pragma unroll
            for (int j = 0; j < 2; j++) {
                float ss = 0.f;
                #pragma unroll
                for (int mt = 0; mt < 4; mt++)
                    ss += acc[mt][nt][j]*acc[mt][nt][j] + acc[mt][nt][2+j]*acc[mt][nt][2+j];
                ss += __shfl_xor_sync(0xffffffffu, ss, 4);
                ss += __shfl_xor_sync(0xffffffffu, ss, 8);
                ss += __shfl_xor_sync(0xffffffffu, ss, 16);
                inv[nt][j] = 1.f / fmaxf(sqrtf(ss), 1e-12f);
            }
        float* dst = (wm ? g_K : g_Q) + (size_t)bidx * CKD * NPIX;
        #pragma unroll
        for (int mt = 0; mt < 4; mt++)
            #pragma unroll
            for (int h = 0; h < 2; h++) {
                int ch = (wm*64 + mt*16 + qr + 8*h) & 63;
                #pragma unroll
                for (int nt = 0; nt < 4; nt++) {
                    int col = n0 + wn*32 + nt*8 + qc;
                    float2 o = make_float2(acc[mt][nt][2*h]   * inv[nt][0],
                                           acc[mt][nt][2*h+1] * inv[nt][1]);
                    *reinterpret_cast<float2*>(&dst[(size_t)ch * NPIX + col]) = o;
                }
            }
    } else {
        float* ob = (MODE == 1) ? g_V : outp;
        const int CROWS = (MODE == 1) ? CIN : COUT;
        #pragma unroll
        for (int mt = 0; mt < 4; mt++)
            #pragma unroll
            for (int h = 0; h < 2; h++) {
                int row = row0 + wm*64 + mt*16 + qr + 8*h;
                float sc = s0[row], bi = b0v[row];
                #pragma unroll
                for (int nt = 0; nt < 4; nt++) {
                    int col = n0 + wn*32 + nt*8 + qc;
                    float2 o;
                    o.x = fmaxf(fmaf(acc[mt][nt][2*h],   sc, bi), 0.f);
                    o.y = fmaxf(fmaf(acc[mt][nt][2*h+1], sc, bi), 0.f);
                    *reinterpret_cast<float2*>(
                        &ob[((size_t)bidx * CROWS + row) * NPIX + col]) = o;
                }
            }
    }
}

// ================= scalar kernels (from R1) =================
__global__ __launch_bounds__(256) void sim_kernel()
{
    __shared__ __align__(16) float As[16][64];
    __shared__ __align__(16) float Bs[16][64];
    const int b = blockIdx.z, chunk = blockIdx.y;
    const int row0 = blockIdx.x * 64;
    const float* V  = g_V + (size_t)b * CIN * NPIX;
    const float* Km = g_K + (size_t)b * CKD * NPIX;
    const int t = threadIdx.x;
    const int tr = t >> 4, tc = t & 15;
    float acc[4][4];
    #pragma unroll
    for (int i = 0; i < 4; i++)
        #pragma unroll
        for (int j = 0; j < 4; j++) acc[i][j] = 0.f;

    const int nb0 = chunk * 512;
    for (int nb = nb0; nb < nb0 + 512; nb += 16) {
        {
            int r  = t >> 2;
            int n4 = (t & 3) << 2;
            float4 va = *reinterpret_cast<const float4*>(V  + (size_t)(row0 + r) * NPIX + nb + n4);
            As[n4+0][r] = va.x; As[n4+1][r] = va.y; As[n4+2][r] = va.z; As[n4+3][r] = va.w;
            float4 vb = *reinterpret_cast<const float4*>(Km + (size_t)r * NPIX + nb + n4);
            Bs[n4+0][r] = vb.x; Bs[n4+1][r] = vb.y; Bs[n4+2][r] = vb.z; Bs[n4+3][r] = vb.w;
        }
        __syncthreads();
        #pragma unroll
        for (int nn = 0; nn < 16; nn++) {
            float4 a = *reinterpret_cast<float4*>(&As[nn][tr*4]);
            float4 bbv = *reinterpret_cast<float4*>(&Bs[nn][tc*4]);
            float av[4] = {a.x,a.y,a.z,a.w};
            float bv[4] = {bbv.x,bbv.y,bbv.z,bbv.w};
            #pragma unroll
            for (int i = 0; i < 4; i++)
                #pragma unroll
                for (int j = 0; j < 4; j++)
                    acc[i][j] = fmaf(av[i], bv[j], acc[i][j]);
        }
        __syncthreads();
    }
    #pragma unroll
    for (int i = 0; i < 4; i++) {
        int c = row0 + tr * 4 + i;
        float4 o = make_float4(acc[i][0], acc[i][1], acc[i][2], acc[i][3]);
        *reinterpret_cast<float4*>(g_simP + ((size_t)(b*8 + chunk) * CIN + c) * CKD + tc*4) = o;
    }
}

__global__ __launch_bounds__(256) void sim_reduce()
{
    int idx = blockIdx.x * 256 + threadIdx.x;
    if (idx >= BB * CIN * CKD) return;
    int b = idx / (CIN * CKD);
    int rem = idx - b * CIN * CKD;
    float s = 0.f;
    #pragma unroll
    for (int p = 0; p < 8; p++)
        s += g_simP[(size_t)(b*8 + p) * CIN * CKD + rem];
    g_simT[idx] = s;
}

__global__ __launch_bounds__(256) void wos_kernel(const float* __restrict__ wo)
{
    __shared__ __align__(16) float As[16][64];
    __shared__ __align__(16) float Bs[16][64];
    const int b = blockIdx.y;
    const int row0 = blockIdx.x * 64;
    const float* ST = g_simT + (size_t)b * CIN * CKD;
    const int t = threadIdx.x;
    const int tr = t >> 4, tc = t & 15;
    float acc[4][4];
    #pragma unroll
    for (int i = 0; i < 4; i++)
        #pragma unroll
        for (int j = 0; j < 4; j++) acc[i][j] = 0.f;

    for (int kb = 0; kb < CIN; kb += 16) {
        {
            int r  = t >> 2;
            int k4 = (t & 3) << 2;
            float4 va = *reinterpret_cast<const float4*>(wo + (size_t)(row0 + r) * CIN + kb + k4);
            As[k4+0][r] = va.x; As[k4+1][r] = va.y; As[k4+2][r] = va.z; As[k4+3][r] = va.w;
            int kk = t >> 4;
            int n4 = (t & 15) << 2;
            *reinterpret_cast<float4*>(&Bs[kk][n4]) =
                *reinterpret_cast<const float4*>(ST + (size_t)(kb + kk) * CKD + n4);
        }
        __syncthreads();
        #pragma unroll
        for (int kk = 0; kk < 16; kk++) {
            float4 a = *reinterpret_cast<float4*>(&As[kk][tr*4]);
            float4 bbv = *reinterpret_cast<float4*>(&Bs[kk][tc*4]);
            float av[4] = {a.x,a.y,a.z,a.w};
            float bv[4] = {bbv.x,bbv.y,bbv.z,bbv.w};
            #pragma unroll
            for (int i = 0; i < 4; i++)
                #pragma unroll
                for (int j = 0; j < 4; j++)
                    acc[i][j] = fmaf(av[i], bv[j], acc[i][j]);
        }
        __syncthreads();
    }
    #pragma unroll
    for (int i = 0; i < 4; i++) {
        int o = row0 + tr * 4 + i;
        float4 ov = make_float4(acc[i][0], acc[i][1], acc[i][2], acc[i][3]);
        *reinterpret_cast<float4*>(g_Wos + (size_t)b * CIN * CKD + (size_t)o * CKD + tc*4) = ov;
    }
}

// ---------------- zero fuseT borders ----------------
__global__ __launch_bounds__(256) void zero_borderT()
{
    int idx = blockIdx.x * 256 + threadIdx.x;
    if (idx >= BB * 260 * 64) return;
    int c16 = idx & 63;
    int r = idx >> 6;
    int b = r / 260, p = r - b * 260;
    int y, x;
    if (p < 66)       { y = 0;  x = p; }
    else if (p < 132) { y = 65; x = p - 66; }
    else if (p < 196) { y = p - 132 + 1; x = 0; }
    else              { y = p - 196 + 1; x = 65; }
    uint4* d = reinterpret_cast<uint4*>(g_fuseT + (((size_t)b*66 + y)*66 + x)*1024) + c16;
    *d = make_uint4(0, 0, 0, 0);
}

// ---------------- fuse = relu(affine(Wos @ Q)) + x + up -> fuseT (split bf16) ----
__global__ __launch_bounds__(256) void fuse_kernel(
    const float* __restrict__ x, const float* __restrict__ up,
    const float* __restrict__ so, const float* __restrict__ bo)
{
    __shared__ __align__(16) float As[16][128];
    __shared__ __align__(16) float Bs[16][64];
    __shared__ float Cs[128][65];
    const int b = blockIdx.z;
    const int row0 = blockIdx.y * 128;
    const int h = blockIdx.x;
    const int col0 = h * 64;
    const float* Wos = g_Wos + (size_t)b * CIN * CKD;
    const float* Qm  = g_Q   + (size_t)b * CKD * NPIX;
    const int t = threadIdx.x;
    const int tr = t >> 4, tc = t & 15;
    float acc[8][4];
    #pragma unroll
    for (int i = 0; i < 8; i++)
        #pragma unroll
        for (int j = 0; j < 4; j++) acc[i][j] = 0.f;

    for (int kb = 0; kb < CKD; kb += 16) {
        #pragma unroll
        for (int q = 0; q < 2; q++) {
            int idx = t * 2 + q;
            int row = idx >> 2;
            int k4  = (idx & 3) << 2;
            float4 v4 = *reinterpret_cast<const float4*>(Wos + (size_t)(row0 + row) * CKD + kb + k4);
            As[k4+0][row] = v4.x; As[k4+1][row] = v4.y;
            As[k4+2][row] = v4.z; As[k4+3][row] = v4.w;
        }
        {
            int kk = t >> 4;
            int n4 = (t & 15) << 2;
            *reinterpret_cast<float4*>(&Bs[kk][n4]) =
                *reinterpret_cast<const float4*>(Qm + (size_t)(kb + kk) * NPIX + col0 + n4);
        }
        __syncthreads();
        #pragma unroll
        for (int kk = 0; kk < 16; kk++) {
            float4 a0 = *reinterpret_cast<float4*>(&As[kk][tr*8]);
            float4 a1 = *reinterpret_cast<float4*>(&As[kk][tr*8+4]);
            float4 b0 = *reinterpret_cast<float4*>(&Bs[kk][tc*4]);
            float av[8] = {a0.x,a0.y,a0.z,a0.w,a1.x,a1.y,a1.z,a1.w};
            float bv[4] = {b0.x,b0.y,b0.z,b0.w};
            #pragma unroll
            for (int i = 0; i < 8; i++)
                #pragma unroll
                for (int j = 0; j < 4; j++)
                    acc[i][j] = fmaf(av[i], bv[j], acc[i][j]);
        }
        __syncthreads();
    }
    #pragma unroll
    for (int i = 0; i < 8; i++) {
        int row = row0 + tr * 8 + i;
        float s = so[row], bi = bo[row];
        size_t xoff = (size_t)b * CIN * NPIX + (size_t)row * NPIX + col0 + tc*4;
        float4 xv = *reinterpret_cast<const float4*>(x + xoff);
        float4 uv = *reinterpret_cast<const float4*>(up + xoff);
        Cs[tr*8+i][tc*4+0] = fmaxf(fmaf(acc[i][0], s, bi), 0.f) + xv.x + uv.x;
        Cs[tr*8+i][tc*4+1] = fmaxf(fmaf(acc[i][1], s, bi), 0.f) + xv.y + uv.y;
        Cs[tr*8+i][tc*4+2] = fmaxf(fmaf(acc[i][2], s, bi), 0.f) + xv.z + uv.z;
        Cs[tr*8+i][tc*4+3] = fmaxf(fmaf(acc[i][3], s, bi), 0.f) + xv.w + uv.w;
    }
    __syncthreads();
    #pragma unroll
    for (int it = 0; it < 4; it++) {
        int task = it * 256 + t;
        int pix = task >> 4, cg = task & 15;
        float f[8];
        #pragma unroll
        for (int j2 = 0; j2 < 8; j2++) f[j2] = Cs[cg*8 + j2][pix];
        unsigned hi[4], lo[4];
        split8(f, hi, lo);
        bf16* d = g_fuseT + (((size_t)b*66 + h + 1)*66 + pix + 1)*1024 + row0 + cg*8;
        *reinterpret_cast<uint4*>(d)       = make_uint4(hi[0], hi[1], hi[2], hi[3]);
        *reinterpret_cast<uint4*>(d + 512) = make_uint4(lo[0], lo[1], lo[2], lo[3]);
    }
}

// ================= launch =================
extern "C" void kernel_launch(void* const* d_in, const int* in_sizes, int n_in,
                              void* d_out, int out_size)
{
    const float* x  = (const float*)d_in[0];
    const float* up = (const float*)d_in[1];
    const float* wq = (const float*)d_in[2];
    const float* sq = (const float*)d_in[3];
    const float* bq = (const float*)d_in[4];
    const float* wk = (const float*)d_in[5];
    const float* sk = (const float*)d_in[6];
    const float* bk = (const float*)d_in[7];
    const float* wv = (const float*)d_in[8];
    const float* sv = (const float*)d_in[9];
    const float* bv = (const float*)d_in[10];
    const float* wo = (const float*)d_in[11];
    const float* so = (const float*)d_in[12];
    const float* bo = (const float*)d_in[13];
    const float* ws = (const float*)d_in[14];
    const float* ss = (const float*)d_in[15];
    const float* bs = (const float*)d_in[16];
    float* out = (float*)d_out;

    prep_split<<<16, 256>>>(wq, 64, 0);
    prep_split<<<16, 256>>>(wk, 64, 1);
    prep_split<<<128, 256>>>(wv, 512, 2);
    prep_wconv<<<288, 256>>>(ws);
    xt_kernel<<<dim3(64, 16, 8), 256>>>(x);
    mma_gemm<0><<<dim3(32, 1, 8), 256>>>(sq, bq, sk, bk, nullptr);
    mma_gemm<1><<<dim3(32, 4, 8), 256>>>(sv, bv, nullptr, nullptr, nullptr);
    sim_kernel<<<dim3(8, 8, 8), 256>>>();
    sim_reduce<<<(BB * CIN * CKD + 255) / 256, 256>>>();
    wos_kernel<<<dim3(8, 8), 256>>>(wo);
    zero_borderT<<<(BB * 260 * 64 + 255) / 256, 256>>>();
    fuse_kernel<<<dim3(64, 4, 8), 256>>>(x, up, so, bo);
    mma_gemm<2><<<dim3(32, 1, 8), 256>>>(ss, bs, nullptr, nullptr, out);
}

// round 5
// speedup vs baseline: 2.6678x; 1.0476x over previous
#include <cuda_runtime.h>
#include <cuda_bf16.h>
#include <math.h>

#define BB 8
#define CIN 512
#define NPIX 4096
#define CKD 64
#define COUT 128
#define KCONV 4608

typedef __nv_bfloat16 bf16;

// ---------------- device scratch ----------------
__device__ __align__(16) bf16 g_XT[(size_t)BB*NPIX*1024];       // [b][n][hi512|lo512]
__device__ __align__(16) bf16 g_fuseT[(size_t)BB*66*66*1024];   // [b][y][x][hi512|lo512]
__device__ __align__(16) bf16 g_Wqk[128*1024];                  // rows: 64 q + 64 k
__device__ __align__(16) bf16 g_Wv[512*1024];
__device__ __align__(16) bf16 g_Wc[128*2*KCONV];                // permuted k'=(r9*512+ic)
__device__ float g_Q[BB*CKD*NPIX];                              // [b][ck][n]
__device__ float g_K[BB*CKD*NPIX];
__device__ float g_V[(size_t)BB*CIN*NPIX];
__device__ float g_simP[BB*8*CIN*CKD];
__device__ float g_simT[BB*CIN*CKD];
__device__ float g_Wos[BB*CIN*CKD];

// ---------------- helpers ----------------
__device__ __forceinline__ unsigned pk2(float a, float b) {
    __nv_bfloat162 h = __floats2bfloat162_rn(a, b);
    return *reinterpret_cast<unsigned*>(&h);
}
__device__ __forceinline__ float bhi_f(float x) { return __bfloat162float(__float2bfloat16_rn(x)); }
__device__ __forceinline__ void split8(const float* f, unsigned* hi, unsigned* lo) {
    #pragma unroll
    for (int i = 0; i < 4; i++) {
        float f0 = f[2*i], f1 = f[2*i+1];
        hi[i] = pk2(f0, f1);
        lo[i] = pk2(f0 - bhi_f(f0), f1 - bhi_f(f1));
    }
}
__device__ __forceinline__ void cpa16(void* sdst, const void* gsrc) {
    unsigned s = (unsigned)__cvta_generic_to_shared(sdst);
    asm volatile("cp.async.cg.shared.global [%0], [%1], 16;" :: "r"(s), "l"(gsrc));
}
__device__ __forceinline__ void cp_commit() { asm volatile("cp.async.commit_group;" ::: "memory"); }
__device__ __forceinline__ void cp_wait1()  { asm volatile("cp.async.wait_group 1;" ::: "memory"); }
__device__ __forceinline__ void cp_wait0()  { asm volatile("cp.async.wait_group 0;" ::: "memory"); }
__device__ __forceinline__ void mma16816(float* d, const unsigned* a, const unsigned* b) {
    asm("mma.sync.aligned.m16n8k16.row.col.f32.bf16.bf16.f32 "
        "{%0,%1,%2,%3},{%4,%5,%6,%7},{%8,%9},{%0,%1,%2,%3};"
        : "+f"(d[0]), "+f"(d[1]), "+f"(d[2]), "+f"(d[3])
        : "r"(a[0]), "r"(a[1]), "r"(a[2]), "r"(a[3]), "r"(b[0]), "r"(b[1]));
}
__device__ __forceinline__ void ldm4(unsigned* r, const bf16* p) {
    unsigned s = (unsigned)__cvta_generic_to_shared(p);
    asm volatile("ldmatrix.sync.aligned.m8n8.x4.shared.b16 {%0,%1,%2,%3}, [%4];"
        : "=r"(r[0]), "=r"(r[1]), "=r"(r[2]), "=r"(r[3]) : "r"(s));
}

// ---------------- prep: split fp32 weights to hi/lo bf16 ----------------
__global__ __launch_bounds__(256) void prep_split(const float* __restrict__ src,
                                                  int rows, int which)
{
    bf16* dst = (which == 0) ? g_Wqk : (which == 1) ? (g_Wqk + 64*1024) : g_Wv;
    int idx = blockIdx.x * 256 + threadIdx.x;
    if (idx >= rows * 64) return;
    int m = idx >> 6, kg = idx & 63;
    float f[8];
    *reinterpret_cast<float4*>(f)     = *reinterpret_cast<const float4*>(src + (size_t)m*512 + kg*8);
    *reinterpret_cast<float4*>(f + 4) = *reinterpret_cast<const float4*>(src + (size_t)m*512 + kg*8 + 4);
    unsigned hi[4], lo[4];
    split8(f, hi, lo);
    bf16* d = dst + (size_t)m * 1024 + kg*8;
    *reinterpret_cast<uint4*>(d)       = make_uint4(hi[0], hi[1], hi[2], hi[3]);
    *reinterpret_cast<uint4*>(d + 512) = make_uint4(lo[0], lo[1], lo[2], lo[3]);
}

// ---------------- prep: conv weights permute + split ----------------
__global__ __launch_bounds__(256) void prep_wconv(const float* __restrict__ ws)
{
    int idx = blockIdx.x * 256 + threadIdx.x;
    if (idx >= 128 * 576) return;
    int oc = idx / 576, kg = idx - oc * 576;
    int kp0 = kg * 8;
    int r9 = kp0 >> 9, ic = kp0 & 511;
    float f[8];
    #pragma unroll
    for (int j = 0; j < 8; j++)
        f[j] = ws[(size_t)oc * KCONV + (ic + j) * 9 + r9];
    unsigned hi[4], lo[4];
    split8(f, hi, lo);
    bf16* d = g_Wc + (size_t)oc * 2 * KCONV + kp0;
    *reinterpret_cast<uint4*>(d)         = make_uint4(hi[0], hi[1], hi[2], hi[3]);
    *reinterpret_cast<uint4*>(d + KCONV) = make_uint4(lo[0], lo[1], lo[2], lo[3]);
}

// ---------------- xt: x[b][c][n] -> XT[b][n][hi|lo] ----------------
__global__ __launch_bounds__(256) void xt_kernel(const float* __restrict__ x)
{
    __shared__ float tile[32][65];
    const int b = blockIdx.z, c0 = blockIdx.y * 32, n0 = blockIdx.x * 64;
    const int t = threadIdx.x;
    {
        int r = t >> 3, nq = (t & 7) * 8;
        const float* src = x + ((size_t)b * CIN + c0 + r) * NPIX + n0 + nq;
        float4 a = *reinterpret_cast<const float4*>(src);
        float4 c = *reinterpret_cast<const float4*>(src + 4);
        tile[r][nq+0]=a.x; tile[r][nq+1]=a.y; tile[r][nq+2]=a.z; tile[r][nq+3]=a.w;
        tile[r][nq+4]=c.x; tile[r][nq+5]=c.y; tile[r][nq+6]=c.z; tile[r][nq+7]=c.w;
    }
    __syncthreads();
    {
        int xc = t & 63, grp = t >> 6;
        float f[8];
        #pragma unroll
        for (int i = 0; i < 8; i++) f[i] = tile[grp*8 + i][xc];
        unsigned hi[4], lo[4];
        split8(f, hi, lo);
        bf16* d = g_XT + ((size_t)b * NPIX + n0 + xc) * 1024 + c0 + grp*8;
        *reinterpret_cast<uint4*>(d)       = make_uint4(hi[0], hi[1], hi[2], hi[3]);
        *reinterpret_cast<uint4*>(d + 512) = make_uint4(lo[0], lo[1], lo[2], lo[3]);
    }
}

// ---------------- big GEMMs via ldmatrix + 64x64 warp tiles ----------------
// CTA 128x128, 4 warps. Tiles per stage: [0]=A-hi [1]=A-lo [2]=B-hi [3]=B-lo.
template<int MODE>
__global__ __launch_bounds__(128) void mma_gemm(
    const float* __restrict__ s0, const float* __restrict__ b0v,
    const float* __restrict__ s1, const float* __restrict__ b1v,
    float* __restrict__ outp)
{
    constexpr int KD = (MODE == 2) ? KCONV : 512;
    constexpr int NSTEP = KD / 16;
    __shared__ __align__(16) bf16 sm[2][4][128][24];   // 48KB
    const int bidx = blockIdx.z;
    const int n0 = blockIdx.x * 128;
    const int row0 = blockIdx.y * 128;
    const int t = threadIdx.x;
    const int lane = t & 31, w = t >> 5, wm = w >> 1, wn = w & 1;

    float acc[4][8][4];
    #pragma unroll
    for (int i = 0; i < 4; i++)
        #pragma unroll
        for (int j = 0; j < 8; j++)
            #pragma unroll
            for (int c = 0; c < 4; c++) acc[i][j][c] = 0.f;

    const bf16* W = (MODE == 0) ? g_Wqk : (MODE == 1) ? g_Wv : g_Wc;
    const bf16* aSrc = W + (size_t)(row0 + t) * (2*KD);
    const bf16* bSrcX = g_XT + ((size_t)bidx * NPIX + n0 + t) * 1024;
    int yi = 0, xi = 0;
    if (MODE == 2) { yi = (n0 + t) >> 6; xi = (n0 + t) & 63; }

    auto load = [&](int st, int kc) {
        cpa16(&sm[st][0][t][0], aSrc + kc);
        cpa16(&sm[st][0][t][8], aSrc + kc + 8);
        cpa16(&sm[st][1][t][0], aSrc + KD + kc);
        cpa16(&sm[st][1][t][8], aSrc + KD + kc + 8);
        const bf16* bp;
        if (MODE == 2) {
            int r9 = kc >> 9, kin = kc & 511;
            int dy = r9 / 3, dx = r9 - dy*3;
            bp = g_fuseT + (((size_t)bidx*66 + yi + dy)*66 + xi + dx)*1024 + kin;
        } else {
            bp = bSrcX + kc;
        }
        cpa16(&sm[st][2][t][0], bp);
        cpa16(&sm[st][2][t][8], bp + 8);
        cpa16(&sm[st][3][t][0], bp + 512);
        cpa16(&sm[st][3][t][8], bp + 512 + 8);
        cp_commit();
    };

    // fragment lane addressing
    const int ar  = wm*64 + (lane & 15);
    const int acl = (lane >> 4) * 8;
    const int br  = wn*64 + ((lane >> 4) << 3) + (lane & 7);
    const int bcl = ((lane >> 3) & 1) * 8;

    load(0, 0);
    #pragma unroll 1
    for (int kt = 0; kt < NSTEP; kt++) {
        int cur = kt & 1;
        if (kt + 1 < NSTEP) { load(cur ^ 1, (kt+1)*16); cp_wait1(); }
        else                 cp_wait0();
        __syncthreads();

        unsigned ah[4][4], al[4][4], bfr[8][2];
        #pragma unroll
        for (int mt = 0; mt < 4; mt++) ldm4(ah[mt], &sm[cur][0][ar + mt*16][acl]);
        #pragma unroll
        for (int mt = 0; mt < 4; mt++) ldm4(al[mt], &sm[cur][1][ar + mt*16][acl]);
        #pragma unroll
        for (int g = 0; g < 4; g++) ldm4(&bfr[2*g][0], &sm[cur][2][br + g*16][bcl]);
        #pragma unroll
        for (int mt = 0; mt < 4; mt++)
            #pragma unroll
            for (int nt = 0; nt < 8; nt++)
                mma16816(acc[mt][nt], ah[mt], bfr[nt]);        // hi*hi
        #pragma unroll
        for (int mt = 0; mt < 4; mt++)
            #pragma unroll
            for (int nt = 0; nt < 8; nt++)
                mma16816(acc[mt][nt], al[mt], bfr[nt]);        // lo*hi
        #pragma unroll
        for (int g = 0; g < 4; g++) ldm4(&bfr[2*g][0], &sm[cur][3][br + g*16][bcl]);
        #pragma unroll
        for (int mt = 0; mt < 4; mt++)
            #pragma unroll
            for (int nt = 0; nt < 8; nt++)
                mma16816(acc[mt][nt], ah[mt], bfr[nt]);        // hi*lo
        __syncthreads();
    }

    const int qr = lane >> 2, qc = (lane & 3) * 2;

    if (MODE == 0) {
        #pragma unroll
        for (int mt = 0; mt < 4; mt++)
            #pragma unroll
            for (int h = 0; h < 2; h++) {
                int ri = (mt*16 + qr + 8*h) & 63;
                float sc = wm ? s1[ri] : s0[ri];
                float bi = wm ? b1v[ri] : b0v[ri];
                #pragma unroll
                for (int nt = 0; nt < 8; nt++) {
                    acc[mt][nt][2*h]   = fmaf(acc[mt][nt][2*h],   sc, bi);
                    acc[mt][nt][2*h+1] = fmaf(acc[mt][nt][2*h+1], sc, bi);
                }
            }
        float inv[8][2];
        #pragma unroll
        for (int nt = 0; nt < 8; nt++)
            #pragma unroll
            for (int j = 0; j < 2; j++) {
                float ss = 0.f;
                #pragma unroll
                for (int mt = 0; mt < 4; mt++)
                    ss += acc[mt][nt][j]*acc[mt][nt][j] + acc[mt][nt][2+j]*acc[mt][nt][2+j];
                ss += __shfl_xor_sync(0xffffffffu, ss, 4);
                ss += __shfl_xor_sync(0xffffffffu, ss, 8);
                ss += __shfl_xor_sync(0xffffffffu, ss, 16);
                inv[nt][j] = 1.f / fmaxf(sqrtf(ss), 1e-12f);
            }
        float* dst = (wm ? g_K : g_Q) + (size_t)bidx * CKD * NPIX;
        #pragma unroll
        for (int mt = 0; mt < 4; mt++)
            #pragma unroll
            for (int h = 0; h < 2; h++) {
                int ch = (mt*16 + qr + 8*h) & 63;
                #pragma unroll
                for (int nt = 0; nt < 8; nt++) {
                    int col = n0 + wn*64 + nt*8 + qc;
                    float2 o = make_float2(acc[mt][nt][2*h]   * inv[nt][0],
                                           acc[mt][nt][2*h+1] * inv[nt][1]);
                    *reinterpret_cast<float2*>(&dst[(size_t)ch * NPIX + col]) = o;
                }
            }
    } else {
        float* ob = (MODE == 1) ? g_V : outp;
        const int CROWS = (MODE == 1) ? CIN : COUT;
        #pragma unroll
        for (int mt = 0; mt < 4; mt++)
            #pragma unroll
            for (int h = 0; h < 2; h++) {
                int row = row0 + wm*64 + mt*16 + qr + 8*h;
                float sc = s0[row], bi = b0v[row];
                #pragma unroll
                for (int nt = 0; nt < 8; nt++) {
                    int col = n0 + wn*64 + nt*8 + qc;
                    float2 o;
                    o.x = fmaxf(fmaf(acc[mt][nt][2*h],   sc, bi), 0.f);
                    o.y = fmaxf(fmaf(acc[mt][nt][2*h+1], sc, bi), 0.f);
                    *reinterpret_cast<float2*>(
                        &ob[((size_t)bidx * CROWS + row) * NPIX + col]) = o;
                }
            }
    }
}

// ================= scalar kernels =================
__global__ __launch_bounds__(256) void sim_kernel()
{
    __shared__ __align__(16) float As[16][64];
    __shared__ __align__(16) float Bs[16][64];
    const int b = blockIdx.z, chunk = blockIdx.y;
    const int row0 = blockIdx.x * 64;
    const float* V  = g_V + (size_t)b * CIN * NPIX;
    const float* Km = g_K + (size_t)b * CKD * NPIX;
    const int t = threadIdx.x;
    const int tr = t >> 4, tc = t & 15;
    float acc[4][4];
    #pragma unroll
    for (int i = 0; i < 4; i++)
        #pragma unroll
        for (int j = 0; j < 4; j++) acc[i][j] = 0.f;

    const int nb0 = chunk * 512;
    for (int nb = nb0; nb < nb0 + 512; nb += 16) {
        {
            int r  = t >> 2;
            int n4 = (t & 3) << 2;
            float4 va = *reinterpret_cast<const float4*>(V  + (size_t)(row0 + r) * NPIX + nb + n4);
            As[n4+0][r] = va.x; As[n4+1][r] = va.y; As[n4+2][r] = va.z; As[n4+3][r] = va.w;
            float4 vb = *reinterpret_cast<const float4*>(Km + (size_t)r * NPIX + nb + n4);
            Bs[n4+0][r] = vb.x; Bs[n4+1][r] = vb.y; Bs[n4+2][r] = vb.z; Bs[n4+3][r] = vb.w;
        }
        __syncthreads();
        #pragma unroll
        for (int nn = 0; nn < 16; nn++) {
            float4 a = *reinterpret_cast<float4*>(&As[nn][tr*4]);
            float4 bbv = *reinterpret_cast<float4*>(&Bs[nn][tc*4]);
            float av[4] = {a.x,a.y,a.z,a.w};
            float bv[4] = {bbv.x,bbv.y,bbv.z,bbv.w};
            #pragma unroll
            for (int i = 0; i < 4; i++)
                #pragma unroll
                for (int j = 0; j < 4; j++)
                    acc[i][j] = fmaf(av[i], bv[j], acc[i][j]);
        }
        __syncthreads();
    }
    #pragma unroll
    for (int i = 0; i < 4; i++) {
        int c = row0 + tr * 4 + i;
        float4 o = make_float4(acc[i][0], acc[i][1], acc[i][2], acc[i][3]);
        *reinterpret_cast<float4*>(g_simP + ((size_t)(b*8 + chunk) * CIN + c) * CKD + tc*4) = o;
    }
}

__global__ __launch_bounds__(256) void sim_reduce()
{
    int idx = blockIdx.x * 256 + threadIdx.x;
    if (idx >= BB * CIN * CKD) return;
    int b = idx / (CIN * CKD);
    int rem = idx - b * CIN * CKD;
    float s = 0.f;
    #pragma unroll
    for (int p = 0; p < 8; p++)
        s += g_simP[(size_t)(b*8 + p) * CIN * CKD + rem];
    g_simT[idx] = s;
}

__global__ __launch_bounds__(256) void wos_kernel(const float* __restrict__ wo)
{
    __shared__ __align__(16) float As[16][64];
    __shared__ __align__(16) float Bs[16][64];
    const int b = blockIdx.y;
    const int row0 = blockIdx.x * 64;
    const float* ST = g_simT + (size_t)b * CIN * CKD;
    const int t = threadIdx.x;
    const int tr = t >> 4, tc = t & 15;
    float acc[4][4];
    #pragma unroll
    for (int i = 0; i < 4; i++)
        #pragma unroll
        for (int j = 0; j < 4; j++) acc[i][j] = 0.f;

    for (int kb = 0; kb < CIN; kb += 16) {
        {
            int r  = t >> 2;
            int k4 = (t & 3) << 2;
            float4 va = *reinterpret_cast<const float4*>(wo + (size_t)(row0 + r) * CIN + kb + k4);
            As[k4+0][r] = va.x; As[k4+1][r] = va.y; As[k4+2][r] = va.z; As[k4+3][r] = va.w;
            int kk = t >> 4;
            int n4 = (t & 15) << 2;
            *reinterpret_cast<float4*>(&Bs[kk][n4]) =
                *reinterpret_cast<const float4*>(ST + (size_t)(kb + kk) * CKD + n4);
        }
        __syncthreads();
        #pragma unroll
        for (int kk = 0; kk < 16; kk++) {
            float4 a = *reinterpret_cast<float4*>(&As[kk][tr*4]);
            float4 bbv = *reinterpret_cast<float4*>(&Bs[kk][tc*4]);
            float av[4] = {a.x,a.y,a.z,a.w};
            float bv[4] = {bbv.x,bbv.y,bbv.z,bbv.w};
            #pragma unroll
            for (int i = 0; i < 4; i++)
                #pragma unroll
                for (int j = 0; j < 4; j++)
                    acc[i][j] = fmaf(av[i], bv[j], acc[i][j]);
        }
        __syncthreads();
    }
    #pragma unroll
    for (int i = 0; i < 4; i++) {
        int o = row0 + tr * 4 + i;
        float4 ov = make_float4(acc[i][0], acc[i][1], acc[i][2], acc[i][3]);
        *reinterpret_cast<float4*>(g_Wos + (size_t)b * CIN * CKD + (size_t)o * CKD + tc*4) = ov;
    }
}

// ---------------- zero fuseT borders ----------------
__global__ __launch_bounds__(256) void zero_borderT()
{
    int idx = blockIdx.x * 256 + threadIdx.x;
    if (idx >= BB * 260 * 64) return;
    int c16 = idx & 63;
    int r = idx >> 6;
    int b = r / 260, p = r - b * 260;
    int y, x;
    if (p < 66)       { y = 0;  x = p; }
    else if (p < 132) { y = 65; x = p - 66; }
    else if (p < 196) { y = p - 132 + 1; x = 0; }
    else              { y = p - 196 + 1; x = 65; }
    uint4* d = reinterpret_cast<uint4*>(g_fuseT + (((size_t)b*66 + y)*66 + x)*1024) + c16;
    *d = make_uint4(0, 0, 0, 0);
}

// ---------------- fuse = relu(affine(Wos @ Q)) + x + up -> fuseT (split bf16) ----
__global__ __launch_bounds__(256) void fuse_kernel(
    const float* __restrict__ x, const float* __restrict__ up,
    const float* __restrict__ so, const float* __restrict__ bo)
{
    __shared__ __align__(16) float As[16][128];
    __shared__ __align__(16) float Bs[16][64];
    __shared__ float Cs[128][65];
    const int b = blockIdx.z;
    const int row0 = blockIdx.y * 128;
    const int h = blockIdx.x;
    const int col0 = h * 64;
    const float* Wos = g_Wos + (size_t)b * CIN * CKD;
    const float* Qm  = g_Q   + (size_t)b * CKD * NPIX;
    const int t = threadIdx.x;
    const int tr = t >> 4, tc = t & 15;
    float acc[8][4];
    #pragma unroll
    for (int i = 0; i < 8; i++)
        #pragma unroll
        for (int j = 0; j < 4; j++) acc[i][j] = 0.f;

    for (int kb = 0; kb < CKD; kb += 16) {
        #pragma unroll
        for (int q = 0; q < 2; q++) {
            int idx = t * 2 + q;
            int row = idx >> 2;
            int k4  = (idx & 3) << 2;
            float4 v4 = *reinterpret_cast<const float4*>(Wos + (size_t)(row0 + row) * CKD + kb + k4);
            As[k4+0][row] = v4.x; As[k4+1][row] = v4.y;
            As[k4+2][row] = v4.z; As[k4+3][row] = v4.w;
        }
        {
            int kk = t >> 4;
            int n4 = (t & 15) << 2;
            *reinterpret_cast<float4*>(&Bs[kk][n4]) =
                *reinterpret_cast<const float4*>(Qm + (size_t)(kb + kk) * NPIX + col0 + n4);
        }
        __syncthreads();
        #pragma unroll
        for (int kk = 0; kk < 16; kk++) {
            float4 a0 = *reinterpret_cast<float4*>(&As[kk][tr*8]);
            float4 a1 = *reinterpret_cast<float4*>(&As[kk][tr*8+4]);
            float4 b0 = *reinterpret_cast<float4*>(&Bs[kk][tc*4]);
            float av[8] = {a0.x,a0.y,a0.z,a0.w,a1.x,a1.y,a1.z,a1.w};
            float bv[4] = {b0.x,b0.y,b0.z,b0.w};
            #pragma unroll
            for (int i = 0; i < 8; i++)
                #pragma unroll
                for (int j = 0; j < 4; j++)
                    acc[i][j] = fmaf(av[i], bv[j], acc[i][j]);
        }
        __syncthreads();
    }
    #pragma unroll
    for (int i = 0; i < 8; i++) {
        int row = row0 + tr * 8 + i;
        float s = so[row], bi = bo[row];
        size_t xoff = (size_t)b * CIN * NPIX + (size_t)row * NPIX + col0 + tc*4;
        float4 xv = *reinterpret_cast<const float4*>(x + xoff);
        float4 uv = *reinterpret_cast<const float4*>(up + xoff);
        Cs[tr*8+i][tc*4+0] = fmaxf(fmaf(acc[i][0], s, bi), 0.f) + xv.x + uv.x;
        Cs[tr*8+i][tc*4+1] = fmaxf(fmaf(acc[i][1], s, bi), 0.f) + xv.y + uv.y;
        Cs[tr*8+i][tc*4+2] = fmaxf(fmaf(acc[i][2], s, bi), 0.f) + xv.z + uv.z;
        Cs[tr*8+i][tc*4+3] = fmaxf(fmaf(acc[i][3], s, bi), 0.f) + xv.w + uv.w;
    }
    __syncthreads();
    #pragma unroll
    for (int it = 0; it < 4; it++) {
        int task = it * 256 + t;
        int pix = task >> 4, cg = task & 15;
        float f[8];
        #pragma unroll
        for (int j2 = 0; j2 < 8; j2++) f[j2] = Cs[cg*8 + j2][pix];
        unsigned hi[4], lo[4];
        split8(f, hi, lo);
        bf16* d = g_fuseT + (((size_t)b*66 + h + 1)*66 + pix + 1)*1024 + row0 + cg*8;
        *reinterpret_cast<uint4*>(d)       = make_uint4(hi[0], hi[1], hi[2], hi[3]);
        *reinterpret_cast<uint4*>(d + 512) = make_uint4(lo[0], lo[1], lo[2], lo[3]);
    }
}

// ================= launch =================
extern "C" void kernel_launch(void* const* d_in, const int* in_sizes, int n_in,
                              void* d_out, int out_size)
{
    const float* x  = (const float*)d_in[0];
    const float* up = (const float*)d_in[1];
    const float* wq = (const float*)d_in[2];
    const float* sq = (const float*)d_in[3];
    const float* bq = (const float*)d_in[4];
    const float* wk = (const float*)d_in[5];
    const float* sk = (const float*)d_in[6];
    const float* bk = (const float*)d_in[7];
    const float* wv = (const float*)d_in[8];
    const float* sv = (const float*)d_in[9];
    const float* bv = (const float*)d_in[10];
    const float* wo = (const float*)d_in[11];
    const float* so = (const float*)d_in[12];
    const float* bo = (const float*)d_in[13];
    const float* ws = (const float*)d_in[14];
    const float* ss = (const float*)d_in[15];
    const float* bs = (const float*)d_in[16];
    float* out = (float*)d_out;

    prep_split<<<16, 256>>>(wq, 64, 0);
    prep_split<<<16, 256>>>(wk, 64, 1);
    prep_split<<<128, 256>>>(wv, 512, 2);
    prep_wconv<<<288, 256>>>(ws);
    xt_kernel<<<dim3(64, 16, 8), 256>>>(x);
    mma_gemm<0><<<dim3(32, 1, 8), 128>>>(sq, bq, sk, bk, nullptr);
    mma_gemm<1><<<dim3(32, 4, 8), 128>>>(sv, bv, nullptr, nullptr, nullptr);
    sim_kernel<<<dim3(8, 8, 8), 256>>>();
    sim_reduce<<<(BB * CIN * CKD + 255) / 256, 256>>>();
    wos_kernel<<<dim3(8, 8), 256>>>(wo);
    zero_borderT<<<(BB * 260 * 64 + 255) / 256, 256>>>();
    fuse_kernel<<<dim3(64, 4, 8), 256>>>(x, up, so, bo);
    mma_gemm<2><<<dim3(32, 1, 8), 128>>>(ss, bs, nullptr, nullptr, out);
}

// round 7
// speedup vs baseline: 2.9375x; 1.1011x over previous
#include <cuda_runtime.h>
#include <cuda_fp16.h>
#include <math.h>

#define BB 8
#define CIN 512
#define NPIX 4096
#define CKD 64
#define COUT 128
#define KCONV 4608

typedef __half h16;

// ---------------- device scratch ----------------
__device__ __align__(16) h16 g_XT[(size_t)BB*NPIX*512];        // [b][n][c512] fp16 (hi only)
__device__ __align__(16) h16 g_fuseT[(size_t)BB*66*66*512];    // [b][y][x][c512] fp16
__device__ __align__(16) h16 g_Wqk[128*1024];                  // [m][hi512|lo512]
__device__ __align__(16) h16 g_Wv[512*1024];
__device__ __align__(16) h16 g_Wc[128*2*KCONV];                // permuted k'=(r9*512+ic), hi|lo
__device__ float g_Q[BB*CKD*NPIX];                             // [b][ck][n]
__device__ float g_K[BB*CKD*NPIX];
__device__ float g_V[(size_t)BB*CIN*NPIX];
__device__ float g_simP[BB*8*CIN*CKD];
__device__ float g_simT[BB*CIN*CKD];
__device__ float g_Wos[BB*CIN*CKD];

// ---------------- helpers ----------------
__device__ __forceinline__ unsigned pk2h(float a, float b) {
    __half2 h = __floats2half2_rn(a, b);
    return *reinterpret_cast<unsigned*>(&h);
}
__device__ __forceinline__ float hhi_f(float x) { return __half2float(__float2half_rn(x)); }
// split 8 floats into fp16 hi (4 words) + fp16 lo (4 words)
__device__ __forceinline__ void split8h(const float* f, unsigned* hi, unsigned* lo) {
    #pragma unroll
    for (int i = 0; i < 4; i++) {
        float f0 = f[2*i], f1 = f[2*i+1];
        hi[i] = pk2h(f0, f1);
        lo[i] = pk2h(f0 - hhi_f(f0), f1 - hhi_f(f1));
    }
}
__device__ __forceinline__ void pack8h(const float* f, unsigned* hi) {
    #pragma unroll
    for (int i = 0; i < 4; i++) hi[i] = pk2h(f[2*i], f[2*i+1]);
}
__device__ __forceinline__ unsigned su32(const void* p) {
    return (unsigned)__cvta_generic_to_shared(p);
}
__device__ __forceinline__ void cpa16(void* sdst, const void* gsrc) {
    asm volatile("cp.async.cg.shared.global [%0], [%1], 16;" :: "r"(su32(sdst)), "l"(gsrc));
}
__device__ __forceinline__ void cp_commit() { asm volatile("cp.async.commit_group;" ::: "memory"); }
__device__ __forceinline__ void cp_wait1()  { asm volatile("cp.async.wait_group 1;" ::: "memory"); }
__device__ __forceinline__ void cp_wait0()  { asm volatile("cp.async.wait_group 0;" ::: "memory"); }
__device__ __forceinline__ void mma16816h(float* d, const unsigned* a, const unsigned* b) {
    asm("mma.sync.aligned.m16n8k16.row.col.f32.f16.f16.f32 "
        "{%0,%1,%2,%3},{%4,%5,%6,%7},{%8,%9},{%0,%1,%2,%3};"
        : "+f"(d[0]), "+f"(d[1]), "+f"(d[2]), "+f"(d[3])
        : "r"(a[0]), "r"(a[1]), "r"(a[2]), "r"(a[3]), "r"(b[0]), "r"(b[1]));
}
__device__ __forceinline__ void ldm4(unsigned* r, const h16* p) {
    asm volatile("ldmatrix.sync.aligned.m8n8.x4.shared.b16 {%0,%1,%2,%3}, [%4];"
        : "=r"(r[0]), "=r"(r[1]), "=r"(r[2]), "=r"(r[3]) : "r"(su32(p)));
}

// ---------------- prep: split fp32 weights to hi/lo fp16 ----------------
__global__ __launch_bounds__(256) void prep_split(const float* __restrict__ src,
                                                  int rows, int which)
{
    h16* dst = (which == 0) ? g_Wqk : (which == 1) ? (g_Wqk + 64*1024) : g_Wv;
    int idx = blockIdx.x * 256 + threadIdx.x;
    if (idx >= rows * 64) return;
    int m = idx >> 6, kg = idx & 63;
    float f[8];
    *reinterpret_cast<float4*>(f)     = *reinterpret_cast<const float4*>(src + (size_t)m*512 + kg*8);
    *reinterpret_cast<float4*>(f + 4) = *reinterpret_cast<const float4*>(src + (size_t)m*512 + kg*8 + 4);
    unsigned hi[4], lo[4];
    split8h(f, hi, lo);
    h16* d = dst + (size_t)m * 1024 + kg*8;
    *reinterpret_cast<uint4*>(d)       = make_uint4(hi[0], hi[1], hi[2], hi[3]);
    *reinterpret_cast<uint4*>(d + 512) = make_uint4(lo[0], lo[1], lo[2], lo[3]);
}

// ---------------- prep: conv weights permute + split ----------------
__global__ __launch_bounds__(256) void prep_wconv(const float* __restrict__ ws)
{
    int idx = blockIdx.x * 256 + threadIdx.x;
    if (idx >= 128 * 576) return;
    int oc = idx / 576, kg = idx - oc * 576;
    int kp0 = kg * 8;
    int r9 = kp0 >> 9, ic = kp0 & 511;
    float f[8];
    #pragma unroll
    for (int j = 0; j < 8; j++)
        f[j] = ws[(size_t)oc * KCONV + (ic + j) * 9 + r9];
    unsigned hi[4], lo[4];
    split8h(f, hi, lo);
    h16* d = g_Wc + (size_t)oc * 2 * KCONV + kp0;
    *reinterpret_cast<uint4*>(d)         = make_uint4(hi[0], hi[1], hi[2], hi[3]);
    *reinterpret_cast<uint4*>(d + KCONV) = make_uint4(lo[0], lo[1], lo[2], lo[3]);
}

// ---------------- xt: x[b][c][n] -> XT[b][n][c] fp16 ----------------
__global__ __launch_bounds__(256) void xt_kernel(const float* __restrict__ x)
{
    __shared__ float tile[32][65];
    const int b = blockIdx.z, c0 = blockIdx.y * 32, n0 = blockIdx.x * 64;
    const int t = threadIdx.x;
    {
        int r = t >> 3, nq = (t & 7) * 8;
        const float* src = x + ((size_t)b * CIN + c0 + r) * NPIX + n0 + nq;
        float4 a = *reinterpret_cast<const float4*>(src);
        float4 c = *reinterpret_cast<const float4*>(src + 4);
        tile[r][nq+0]=a.x; tile[r][nq+1]=a.y; tile[r][nq+2]=a.z; tile[r][nq+3]=a.w;
        tile[r][nq+4]=c.x; tile[r][nq+5]=c.y; tile[r][nq+6]=c.z; tile[r][nq+7]=c.w;
    }
    __syncthreads();
    {
        int xc = t & 63, grp = t >> 6;
        float f[8];
        #pragma unroll
        for (int i = 0; i < 8; i++) f[i] = tile[grp*8 + i][xc];
        unsigned hh[4];
        pack8h(f, hh);
        h16* d = g_XT + ((size_t)b * NPIX + n0 + xc) * 512 + c0 + grp*8;
        *reinterpret_cast<uint4*>(d) = make_uint4(hh[0], hh[1], hh[2], hh[3]);
    }
}

// ---------------- big GEMMs: 2-pass fp16, ldmatrix, 64x64 warp tiles ----------------
// CTA 128x128, 4 warps. Tiles per stage: [0]=A-hi [1]=A-lo [2]=B.
template<int MODE>
__global__ __launch_bounds__(128) void mma_gemm(
    const float* __restrict__ s0, const float* __restrict__ b0v,
    const float* __restrict__ s1, const float* __restrict__ b1v,
    float* __restrict__ outp)
{
    constexpr int KD = (MODE == 2) ? KCONV : 512;
    constexpr int NSTEP = KD / 16;
    __shared__ __align__(16) h16 sm[2][3][128][24];   // 36KB
    const int bidx = blockIdx.z;
    const int n0 = blockIdx.x * 128;
    const int row0 = blockIdx.y * 128;
    const int t = threadIdx.x;
    const int lane = t & 31, w = t >> 5, wm = w >> 1, wn = w & 1;

    float acc[4][8][4];
    #pragma unroll
    for (int i = 0; i < 4; i++)
        #pragma unroll
        for (int j = 0; j < 8; j++)
            #pragma unroll
            for (int c = 0; c < 4; c++) acc[i][j][c] = 0.f;

    const h16* W = (MODE == 0) ? g_Wqk : (MODE == 1) ? g_Wv : g_Wc;
    const h16* aSrc = W + (size_t)(row0 + t) * (2*KD);
    const h16* bSrcX = g_XT + ((size_t)bidx * NPIX + n0 + t) * 512;
    int yi = 0, xi = 0;
    if (MODE == 2) { int p = n0 + t; yi = p >> 6; xi = p & 63; }

    auto load = [&](int st, int kc) {
        cpa16(&sm[st][0][t][0], aSrc + kc);
        cpa16(&sm[st][0][t][8], aSrc + kc + 8);
        cpa16(&sm[st][1][t][0], aSrc + KD + kc);
        cpa16(&sm[st][1][t][8], aSrc + KD + kc + 8);
        const h16* bp;
        if (MODE == 2) {
            int r9 = kc >> 9, kin = kc & 511;
            int dy = r9 / 3, dx = r9 - dy*3;
            bp = g_fuseT + (((size_t)bidx*66 + yi + dy)*66 + xi + dx)*512 + kin;
        } else {
            bp = bSrcX + kc;
        }
        cpa16(&sm[st][2][t][0], bp);
        cpa16(&sm[st][2][t][8], bp + 8);
        cp_commit();
    };

    const int ar  = wm*64 + (lane & 15);
    const int acl = (lane >> 4) * 8;
    const int br  = wn*64 + ((lane >> 4) << 3) + (lane & 7);
    const int bcl = ((lane >> 3) & 1) * 8;

    load(0, 0);
    #pragma unroll 1
    for (int kt = 0; kt < NSTEP; kt++) {
        int cur = kt & 1;
        if (kt + 1 < NSTEP) { load(cur ^ 1, (kt+1)*16); cp_wait1(); }
        else                 cp_wait0();
        __syncthreads();

        unsigned ah[4][4], al[4][4], bfr[8][2];
        #pragma unroll
        for (int mt = 0; mt < 4; mt++) ldm4(ah[mt], &sm[cur][0][ar + mt*16][acl]);
        #pragma unroll
        for (int mt = 0; mt < 4; mt++) ldm4(al[mt], &sm[cur][1][ar + mt*16][acl]);
        #pragma unroll
        for (int g = 0; g < 4; g++) ldm4(&bfr[2*g][0], &sm[cur][2][br + g*16][bcl]);
        #pragma unroll
        for (int mt = 0; mt < 4; mt++)
            #pragma unroll
            for (int nt = 0; nt < 8; nt++)
                mma16816h(acc[mt][nt], ah[mt], bfr[nt]);       // hi*B
        #pragma unroll
        for (int mt = 0; mt < 4; mt++)
            #pragma unroll
            for (int nt = 0; nt < 8; nt++)
                mma16816h(acc[mt][nt], al[mt], bfr[nt]);       // lo*B
        __syncthreads();
    }

    const int qr = lane >> 2, qc = (lane & 3) * 2;

    if (MODE == 0) {
        #pragma unroll
        for (int mt = 0; mt < 4; mt++)
            #pragma unroll
            for (int h = 0; h < 2; h++) {
                int ri = (mt*16 + qr + 8*h) & 63;
                float sc = wm ? s1[ri] : s0[ri];
                float bi = wm ? b1v[ri] : b0v[ri];
                #pragma unroll
                for (int nt = 0; nt < 8; nt++) {
                    acc[mt][nt][2*h]   = fmaf(acc[mt][nt][2*h],   sc, bi);
                    acc[mt][nt][2*h+1] = fmaf(acc[mt][nt][2*h+1], sc, bi);
                }
            }
        float inv[8][2];
        #pragma unroll
        for (int nt = 0; nt < 8; nt++)
            #pragma unroll
            for (int j = 0; j < 2; j++) {
                float ss = 0.f;
                #pragma unroll
                for (int mt = 0; mt < 4; mt++)
                    ss += acc[mt][nt][j]*acc[mt][nt][j] + acc[mt][nt][2+j]*acc[mt][nt][2+j];
                ss += __shfl_xor_sync(0xffffffffu, ss, 4);
                ss += __shfl_xor_sync(0xffffffffu, ss, 8);
                ss += __shfl_xor_sync(0xffffffffu, ss, 16);
                inv[nt][j] = 1.f / fmaxf(sqrtf(ss), 1e-12f);
            }
        float* dst = (wm ? g_K : g_Q) + (size_t)bidx * CKD * NPIX;
        #pragma unroll
        for (int mt = 0; mt < 4; mt++)
            #pragma unroll
            for (int h = 0; h < 2; h++) {
                int ch = (mt*16 + qr + 8*h) & 63;
                #pragma unroll
                for (int nt = 0; nt < 8; nt++) {
                    int col = n0 + wn*64 + nt*8 + qc;
                    float2 o = make_float2(acc[mt][nt][2*h]   * inv[nt][0],
                                           acc[mt][nt][2*h+1] * inv[nt][1]);
                    *reinterpret_cast<float2*>(&dst[(size_t)ch * NPIX + col]) = o;
                }
            }
    } else {
        float* ob = (MODE == 1) ? g_V : outp;
        const int CROWS = (MODE == 1) ? CIN : COUT;
        #pragma unroll
        for (int mt = 0; mt < 4; mt++)
            #pragma unroll
            for (int h = 0; h < 2; h++) {
                int row = row0 + wm*64 + mt*16 + qr + 8*h;
                float sc = s0[row], bi = b0v[row];
                #pragma unroll
                for (int nt = 0; nt < 8; nt++) {
                    int col = n0 + wn*64 + nt*8 + qc;
                    float2 o;
                    o.x = fmaxf(fmaf(acc[mt][nt][2*h],   sc, bi), 0.f);
                    o.y = fmaxf(fmaf(acc[mt][nt][2*h+1], sc, bi), 0.f);
                    *reinterpret_cast<float2*>(
                        &ob[((size_t)bidx * CROWS + row) * NPIX + col]) = o;
                }
            }
    }
}

// ================= scalar kernels =================
__global__ __launch_bounds__(256) void sim_kernel()
{
    __shared__ __align__(16) float As[16][64];
    __shared__ __align__(16) float Bs[16][64];
    const int b = blockIdx.z, chunk = blockIdx.y;
    const int row0 = blockIdx.x * 64;
    const float* V  = g_V + (size_t)b * CIN * NPIX;
    const float* Km = g_K + (size_t)b * CKD * NPIX;
    const int t = threadIdx.x;
    const int tr = t >> 4, tc = t & 15;
    float acc[4][4];
    #pragma unroll
    for (int i = 0; i < 4; i++)
        #pragma unroll
        for (int j = 0; j < 4; j++) acc[i][j] = 0.f;

    const int nb0 = chunk * 512;
    for (int nb = nb0; nb < nb0 + 512; nb += 16) {
        {
            int r  = t >> 2;
            int n4 = (t & 3) << 2;
            float4 va = *reinterpret_cast<const float4*>(V  + (size_t)(row0 + r) * NPIX + nb + n4);
            As[n4+0][r] = va.x; As[n4+1][r] = va.y; As[n4+2][r] = va.z; As[n4+3][r] = va.w;
            float4 vb = *reinterpret_cast<const float4*>(Km + (size_t)r * NPIX + nb + n4);
            Bs[n4+0][r] = vb.x; Bs[n4+1][r] = vb.y; Bs[n4+2][r] = vb.z; Bs[n4+3][r] = vb.w;
        }
        __syncthreads();
        #pragma unroll
        for (int nn = 0; nn < 16; nn++) {
            float4 a = *reinterpret_cast<float4*>(&As[nn][tr*4]);
            float4 bbv = *reinterpret_cast<float4*>(&Bs[nn][tc*4]);
            float av[4] = {a.x,a.y,a.z,a.w};
            float bv[4] = {bbv.x,bbv.y,bbv.z,bbv.w};
            #pragma unroll
            for (int i = 0; i < 4; i++)
                #pragma unroll
                for (int j = 0; j < 4; j++)
                    acc[i][j] = fmaf(av[i], bv[j], acc[i][j]);
        }
        __syncthreads();
    }
    #pragma unroll
    for (int i = 0; i < 4; i++) {
        int c = row0 + tr * 4 + i;
        float4 o = make_float4(acc[i][0], acc[i][1], acc[i][2], acc[i][3]);
        *reinterpret_cast<float4*>(g_simP + ((size_t)(b*8 + chunk) * CIN + c) * CKD + tc*4) = o;
    }
}

__global__ __launch_bounds__(256) void sim_reduce()
{
    int idx = blockIdx.x * 256 + threadIdx.x;
    if (idx >= BB * CIN * CKD) return;
    int b = idx / (CIN * CKD);
    int rem = idx - b * CIN * CKD;
    float s = 0.f;
    #pragma unroll
    for (int p = 0; p < 8; p++)
        s += g_simP[(size_t)(b*8 + p) * CIN * CKD + rem];
    g_simT[idx] = s;
}

__global__ __launch_bounds__(256) void wos_kernel(const float* __restrict__ wo)
{
    __shared__ __align__(16) float As[16][64];
    __shared__ __align__(16) float Bs[16][64];
    const int b = blockIdx.y;
    const int row0 = blockIdx.x * 64;
    const float* ST = g_simT + (size_t)b * CIN * CKD;
    const int t = threadIdx.x;
    const int tr = t >> 4, tc = t & 15;
    float acc[4][4];
    #pragma unroll
    for (int i = 0; i < 4; i++)
        #pragma unroll
        for (int j = 0; j < 4; j++) acc[i][j] = 0.f;

    for (int kb = 0; kb < CIN; kb += 16) {
        {
            int r  = t >> 2;
            int k4 = (t & 3) << 2;
            float4 va = *reinterpret_cast<const float4*>(wo + (size_t)(row0 + r) * CIN + kb + k4);
            As[k4+0][r] = va.x; As[k4+1][r] = va.y; As[k4+2][r] = va.z; As[k4+3][r] = va.w;
            int kk = t >> 4;
            int n4 = (t & 15) << 2;
            *reinterpret_cast<float4*>(&Bs[kk][n4]) =
                *reinterpret_cast<const float4*>(ST + (size_t)(kb + kk) * CKD + n4);
        }
        __syncthreads();
        #pragma unroll
        for (int kk = 0; kk < 16; kk++) {
            float4 a = *reinterpret_cast<float4*>(&As[kk][tr*4]);
            float4 bbv = *reinterpret_cast<float4*>(&Bs[kk][tc*4]);
            float av[4] = {a.x,a.y,a.z,a.w};
            float bv[4] = {bbv.x,bbv.y,bbv.z,bbv.w};
            #pragma unroll
            for (int i = 0; i < 4; i++)
                #pragma unroll
                for (int j = 0; j < 4; j++)
                    acc[i][j] = fmaf(av[i], bv[j], acc[i][j]);
        }
        __syncthreads();
    }
    #pragma unroll
    for (int i = 0; i < 4; i++) {
        int o = row0 + tr * 4 + i;
        float4 ov = make_float4(acc[i][0], acc[i][1], acc[i][2], acc[i][3]);
        *reinterpret_cast<float4*>(g_Wos + (size_t)b * CIN * CKD + (size_t)o * CKD + tc*4) = ov;
    }
}

// ---------------- zero fuseT borders (64 uint4 = full 512 fp16 per pixel) --------
__global__ __launch_bounds__(256) void zero_borderT()
{
    int idx = blockIdx.x * 256 + threadIdx.x;
    if (idx >= BB * 260 * 64) return;
    int c16 = idx & 63;
    int r = idx >> 6;
    int b = r / 260, p = r - b * 260;
    int y, x;
    if (p < 66)       { y = 0;  x = p; }
    else if (p < 132) { y = 65; x = p - 66; }
    else if (p < 196) { y = p - 132 + 1; x = 0; }
    else              { y = p - 196 + 1; x = 65; }
    uint4* d = reinterpret_cast<uint4*>(g_fuseT + (((size_t)b*66 + y)*66 + x)*512);
    // 512 fp16 = 1024B = 64 uint4; each thread covers one
    d[c16] = make_uint4(0, 0, 0, 0);
}

// ---------------- fuse = relu(affine(Wos @ Q)) + x + up -> fuseT (fp16) ----------
__global__ __launch_bounds__(256) void fuse_kernel(
    const float* __restrict__ x, const float* __restrict__ up,
    const float* __restrict__ so, const float* __restrict__ bo)
{
    __shared__ __align__(16) float As[16][128];
    __shared__ __align__(16) float Bs[16][64];
    __shared__ float Cs[128][65];
    const int b = blockIdx.z;
    const int row0 = blockIdx.y * 128;
    const int h = blockIdx.x;
    const int col0 = h * 64;
    const float* Wos = g_Wos + (size_t)b * CIN * CKD;
    const float* Qm  = g_Q   + (size_t)b * CKD * NPIX;
    const int t = threadIdx.x;
    const int tr = t >> 4, tc = t & 15;
    float acc[8][4];
    #pragma unroll
    for (int i = 0; i < 8; i++)
        #pragma unroll
        for (int j = 0; j < 4; j++) acc[i][j] = 0.f;

    for (int kb = 0; kb < CKD; kb += 16) {
        #pragma unroll
        for (int q = 0; q < 2; q++) {
            int idx = t * 2 + q;
            int row = idx >> 2;
            int k4  = (idx & 3) << 2;
            float4 v4 = *reinterpret_cast<const float4*>(Wos + (size_t)(row0 + row) * CKD + kb + k4);
            As[k4+0][row] = v4.x; As[k4+1][row] = v4.y;
            As[k4+2][row] = v4.z; As[k4+3][row] = v4.w;
        }
        {
            int kk = t >> 4;
            int n4 = (t & 15) << 2;
            *reinterpret_cast<float4*>(&Bs[kk][n4]) =
                *reinterpret_cast<const float4*>(Qm + (size_t)(kb + kk) * NPIX + col0 + n4);
        }
        __syncthreads();
        #pragma unroll
        for (int kk = 0; kk < 16; kk++) {
            float4 a0 = *reinterpret_cast<float4*>(&As[kk][tr*8]);
            float4 a1 = *reinterpret_cast<float4*>(&As[kk][tr*8+4]);
            float4 b0 = *reinterpret_cast<float4*>(&Bs[kk][tc*4]);
            float av[8] = {a0.x,a0.y,a0.z,a0.w,a1.x,a1.y,a1.z,a1.w};
            float bv[4] = {b0.x,b0.y,b0.z,b0.w};
            #pragma unroll
            for (int i = 0; i < 8; i++)
                #pragma unroll
                for (int j = 0; j < 4; j++)
                    acc[i][j] = fmaf(av[i], bv[j], acc[i][j]);
        }
        __syncthreads();
    }
    #pragma unroll
    for (int i = 0; i < 8; i++) {
        int row = row0 + tr * 8 + i;
        float s = so[row], bi = bo[row];
        size_t xoff = (size_t)b * CIN * NPIX + (size_t)row * NPIX + col0 + tc*4;
        float4 xv = *reinterpret_cast<const float4*>(x + xoff);
        float4 uv = *reinterpret_cast<const float4*>(up + xoff);
        Cs[tr*8+i][tc*4+0] = fmaxf(fmaf(acc[i][0], s, bi), 0.f) + xv.x + uv.x;
        Cs[tr*8+i][tc*4+1] = fmaxf(fmaf(acc[i][1], s, bi), 0.f) + xv.y + uv.y;
        Cs[tr*8+i][tc*4+2] = fmaxf(fmaf(acc[i][2], s, bi), 0.f) + xv.z + uv.z;
        Cs[tr*8+i][tc*4+3] = fmaxf(fmaf(acc[i][3], s, bi), 0.f) + xv.w + uv.w;
    }
    __syncthreads();
    #pragma unroll
    for (int it = 0; it < 4; it++) {
        int task = it * 256 + t;
        int pix = task >> 4, cg = task & 15;
        float f[8];
        #pragma unroll
        for (int j2 = 0; j2 < 8; j2++) f[j2] = Cs[cg*8 + j2][pix];
        unsigned hh[4];
        pack8h(f, hh);
        h16* d = g_fuseT + (((size_t)b*66 + h + 1)*66 + pix + 1)*512 + row0 + cg*8;
        *reinterpret_cast<uint4*>(d) = make_uint4(hh[0], hh[1], hh[2], hh[3]);
    }
}

// ================= launch =================
extern "C" void kernel_launch(void* const* d_in, const int* in_sizes, int n_in,
                              void* d_out, int out_size)
{
    const float* x  = (const float*)d_in[0];
    const float* up = (const float*)d_in[1];
    const float* wq = (const float*)d_in[2];
    const float* sq = (const float*)d_in[3];
    const float* bq = (const float*)d_in[4];
    const float* wk = (const float*)d_in[5];
    const float* sk = (const float*)d_in[6];
    const float* bk = (const float*)d_in[7];
    const float* wv = (const float*)d_in[8];
    const float* sv = (const float*)d_in[9];
    const float* bv = (const float*)d_in[10];
    const float* wo = (const float*)d_in[11];
    const float* so = (const float*)d_in[12];
    const float* bo = (const float*)d_in[13];
    const float* ws = (const float*)d_in[14];
    const float* ss = (const float*)d_in[15];
    const float* bs = (const float*)d_in[16];
    float* out = (float*)d_out;

    prep_split<<<16, 256>>>(wq, 64, 0);
    prep_split<<<16, 256>>>(wk, 64, 1);
    prep_split<<<128, 256>>>(wv, 512, 2);
    prep_wconv<<<288, 256>>>(ws);
    xt_kernel<<<dim3(64, 16, 8), 256>>>(x);
    mma_gemm<0><<<dim3(32, 1, 8), 128>>>(sq, bq, sk, bk, nullptr);
    mma_gemm<1><<<dim3(32, 4, 8), 128>>>(sv, bv, nullptr, nullptr, nullptr);
    sim_kernel<<<dim3(8, 8, 8), 256>>>();
    sim_reduce<<<(BB * CIN * CKD + 255) / 256, 256>>>();
    wos_kernel<<<dim3(8, 8), 256>>>(wo);
    zero_borderT<<<(BB * 260 * 64 + 255) / 256, 256>>>();
    fuse_kernel<<<dim3(64, 4, 8), 256>>>(x, up, so, bo);
    mma_gemm<2><<<dim3(32, 1, 8), 128>>>(ss, bs, nullptr, nullptr, out);
}

// round 8
// speedup vs baseline: 3.0328x; 1.0325x over previous
#include <cuda_runtime.h>
#include <cuda_fp16.h>
#include <math.h>

#define BB 8
#define CIN 512
#define NPIX 4096
#define CKD 64
#define COUT 128
#define KCONV 4608

typedef __half h16;

// ---------------- device scratch ----------------
__device__ __align__(16) h16 g_XT[(size_t)BB*NPIX*512];        // [b][n][c512] fp16
__device__ __align__(16) h16 g_fuseT[(size_t)BB*66*66*512];    // [b][y][x][c512] fp16
__device__ __align__(16) h16 g_Wqk[128*1024];                  // [m][hi512|lo512]
__device__ __align__(16) h16 g_Wv[512*1024];
__device__ __align__(16) h16 g_Wc[128*2*KCONV];                // permuted k'=(r9*512+ic), hi|lo
__device__ __align__(16) h16 g_Vh[(size_t)BB*CIN*2*NPIX];      // [b][c][hi|lo][n]
__device__ __align__(16) h16 g_Kh[(size_t)BB*CKD*2*NPIX];      // [b][k][hi|lo][n]
__device__ float g_Q[BB*CKD*NPIX];                             // [b][ck][n] fp32 (fuse needs it)
__device__ float g_simP[BB*4*CIN*CKD];
__device__ float g_simT[BB*CIN*CKD];
__device__ float g_Wos[BB*CIN*CKD];

// ---------------- helpers ----------------
__device__ __forceinline__ unsigned pk2h(float a, float b) {
    __half2 h = __floats2half2_rn(a, b);
    return *reinterpret_cast<unsigned*>(&h);
}
__device__ __forceinline__ float hhi_f(float x) { return __half2float(__float2half_rn(x)); }
__device__ __forceinline__ void split8h(const float* f, unsigned* hi, unsigned* lo) {
    #pragma unroll
    for (int i = 0; i < 4; i++) {
        float f0 = f[2*i], f1 = f[2*i+1];
        hi[i] = pk2h(f0, f1);
        lo[i] = pk2h(f0 - hhi_f(f0), f1 - hhi_f(f1));
    }
}
__device__ __forceinline__ void pack8h(const float* f, unsigned* hi) {
    #pragma unroll
    for (int i = 0; i < 4; i++) hi[i] = pk2h(f[2*i], f[2*i+1]);
}
__device__ __forceinline__ unsigned su32(const void* p) {
    return (unsigned)__cvta_generic_to_shared(p);
}
__device__ __forceinline__ void cpa16(void* sdst, const void* gsrc) {
    asm volatile("cp.async.cg.shared.global [%0], [%1], 16;" :: "r"(su32(sdst)), "l"(gsrc));
}
__device__ __forceinline__ void cp_commit() { asm volatile("cp.async.commit_group;" ::: "memory"); }
__device__ __forceinline__ void cp_wait1()  { asm volatile("cp.async.wait_group 1;" ::: "memory"); }
__device__ __forceinline__ void cp_wait0()  { asm volatile("cp.async.wait_group 0;" ::: "memory"); }
__device__ __forceinline__ void mma16816h(float* d, const unsigned* a, const unsigned* b) {
    asm("mma.sync.aligned.m16n8k16.row.col.f32.f16.f16.f32 "
        "{%0,%1,%2,%3},{%4,%5,%6,%7},{%8,%9},{%0,%1,%2,%3};"
        : "+f"(d[0]), "+f"(d[1]), "+f"(d[2]), "+f"(d[3])
        : "r"(a[0]), "r"(a[1]), "r"(a[2]), "r"(a[3]), "r"(b[0]), "r"(b[1]));
}
__device__ __forceinline__ void ldm4(unsigned* r, const h16* p) {
    asm volatile("ldmatrix.sync.aligned.m8n8.x4.shared.b16 {%0,%1,%2,%3}, [%4];"
        : "=r"(r[0]), "=r"(r[1]), "=r"(r[2]), "=r"(r[3]) : "r"(su32(p)));
}

// ---------------- prep: split fp32 weights to hi/lo fp16 ----------------
__global__ __launch_bounds__(256) void prep_split(const float* __restrict__ src,
                                                  int rows, int which)
{
    h16* dst = (which == 0) ? g_Wqk : (which == 1) ? (g_Wqk + 64*1024) : g_Wv;
    int idx = blockIdx.x * 256 + threadIdx.x;
    if (idx >= rows * 64) return;
    int m = idx >> 6, kg = idx & 63;
    float f[8];
    *reinterpret_cast<float4*>(f)     = *reinterpret_cast<const float4*>(src + (size_t)m*512 + kg*8);
    *reinterpret_cast<float4*>(f + 4) = *reinterpret_cast<const float4*>(src + (size_t)m*512 + kg*8 + 4);
    unsigned hi[4], lo[4];
    split8h(f, hi, lo);
    h16* d = dst + (size_t)m * 1024 + kg*8;
    *reinterpret_cast<uint4*>(d)       = make_uint4(hi[0], hi[1], hi[2], hi[3]);
    *reinterpret_cast<uint4*>(d + 512) = make_uint4(lo[0], lo[1], lo[2], lo[3]);
}

// ---------------- prep: conv weights permute + split ----------------
__global__ __launch_bounds__(256) void prep_wconv(const float* __restrict__ ws)
{
    int idx = blockIdx.x * 256 + threadIdx.x;
    if (idx >= 128 * 576) return;
    int oc = idx / 576, kg = idx - oc * 576;
    int kp0 = kg * 8;
    int r9 = kp0 >> 9, ic = kp0 & 511;
    float f[8];
    #pragma unroll
    for (int j = 0; j < 8; j++)
        f[j] = ws[(size_t)oc * KCONV + (ic + j) * 9 + r9];
    unsigned hi[4], lo[4];
    split8h(f, hi, lo);
    h16* d = g_Wc + (size_t)oc * 2 * KCONV + kp0;
    *reinterpret_cast<uint4*>(d)         = make_uint4(hi[0], hi[1], hi[2], hi[3]);
    *reinterpret_cast<uint4*>(d + KCONV) = make_uint4(lo[0], lo[1], lo[2], lo[3]);
}

// ---------------- xt: x[b][c][n] -> XT[b][n][c] fp16 ----------------
__global__ __launch_bounds__(256) void xt_kernel(const float* __restrict__ x)
{
    __shared__ float tile[32][65];
    const int b = blockIdx.z, c0 = blockIdx.y * 32, n0 = blockIdx.x * 64;
    const int t = threadIdx.x;
    {
        int r = t >> 3, nq = (t & 7) * 8;
        const float* src = x + ((size_t)b * CIN + c0 + r) * NPIX + n0 + nq;
        float4 a = *reinterpret_cast<const float4*>(src);
        float4 c = *reinterpret_cast<const float4*>(src + 4);
        tile[r][nq+0]=a.x; tile[r][nq+1]=a.y; tile[r][nq+2]=a.z; tile[r][nq+3]=a.w;
        tile[r][nq+4]=c.x; tile[r][nq+5]=c.y; tile[r][nq+6]=c.z; tile[r][nq+7]=c.w;
    }
    __syncthreads();
    {
        int xc = t & 63, grp = t >> 6;
        float f[8];
        #pragma unroll
        for (int i = 0; i < 8; i++) f[i] = tile[grp*8 + i][xc];
        unsigned hh[4];
        pack8h(f, hh);
        h16* d = g_XT + ((size_t)b * NPIX + n0 + xc) * 512 + c0 + grp*8;
        *reinterpret_cast<uint4*>(d) = make_uint4(hh[0], hh[1], hh[2], hh[3]);
    }
}

// ---------------- big GEMMs: 2-pass fp16, ldmatrix, 64x64 warp tiles ----------------
template<int MODE>
__global__ __launch_bounds__(128) void mma_gemm(
    const float* __restrict__ s0, const float* __restrict__ b0v,
    const float* __restrict__ s1, const float* __restrict__ b1v,
    float* __restrict__ outp)
{
    constexpr int KD = (MODE == 2) ? KCONV : 512;
    constexpr int NSTEP = KD / 16;
    __shared__ __align__(16) h16 sm[2][3][128][24];   // 36KB
    const int bidx = blockIdx.z;
    const int n0 = blockIdx.x * 128;
    const int row0 = blockIdx.y * 128;
    const int t = threadIdx.x;
    const int lane = t & 31, w = t >> 5, wm = w >> 1, wn = w & 1;

    float acc[4][8][4];
    #pragma unroll
    for (int i = 0; i < 4; i++)
        #pragma unroll
        for (int j = 0; j < 8; j++)
            #pragma unroll
            for (int c = 0; c < 4; c++) acc[i][j][c] = 0.f;

    const h16* W = (MODE == 0) ? g_Wqk : (MODE == 1) ? g_Wv : g_Wc;
    const h16* aSrc = W + (size_t)(row0 + t) * (2*KD);
    const h16* bSrcX = g_XT + ((size_t)bidx * NPIX + n0 + t) * 512;
    int yi = 0, xi = 0;
    if (MODE == 2) { int p = n0 + t; yi = p >> 6; xi = p & 63; }

    auto load = [&](int st, int kc) {
        cpa16(&sm[st][0][t][0], aSrc + kc);
        cpa16(&sm[st][0][t][8], aSrc + kc + 8);
        cpa16(&sm[st][1][t][0], aSrc + KD + kc);
        cpa16(&sm[st][1][t][8], aSrc + KD + kc + 8);
        const h16* bp;
        if (MODE == 2) {
            int r9 = kc >> 9, kin = kc & 511;
            int dy = r9 / 3, dx = r9 - dy*3;
            bp = g_fuseT + (((size_t)bidx*66 + yi + dy)*66 + xi + dx)*512 + kin;
        } else {
            bp = bSrcX + kc;
        }
        cpa16(&sm[st][2][t][0], bp);
        cpa16(&sm[st][2][t][8], bp + 8);
        cp_commit();
    };

    const int ar  = wm*64 + (lane & 15);
    const int acl = (lane >> 4) * 8;
    const int br  = wn*64 + ((lane >> 4) << 3) + (lane & 7);
    const int bcl = ((lane >> 3) & 1) * 8;

    load(0, 0);
    #pragma unroll 1
    for (int kt = 0; kt < NSTEP; kt++) {
        int cur = kt & 1;
        if (kt + 1 < NSTEP) { load(cur ^ 1, (kt+1)*16); cp_wait1(); }
        else                 cp_wait0();
        __syncthreads();

        unsigned ah[4][4], al[4][4], bfr[8][2];
        #pragma unroll
        for (int mt = 0; mt < 4; mt++) ldm4(ah[mt], &sm[cur][0][ar + mt*16][acl]);
        #pragma unroll
        for (int mt = 0; mt < 4; mt++) ldm4(al[mt], &sm[cur][1][ar + mt*16][acl]);
        #pragma unroll
        for (int g = 0; g < 4; g++) ldm4(&bfr[2*g][0], &sm[cur][2][br + g*16][bcl]);
        #pragma unroll
        for (int mt = 0; mt < 4; mt++)
            #pragma unroll
            for (int nt = 0; nt < 8; nt++)
                mma16816h(acc[mt][nt], ah[mt], bfr[nt]);       // hi*B
        #pragma unroll
        for (int mt = 0; mt < 4; mt++)
            #pragma unroll
            for (int nt = 0; nt < 8; nt++)
                mma16816h(acc[mt][nt], al[mt], bfr[nt]);       // lo*B
        __syncthreads();
    }

    const int qr = lane >> 2, qc = (lane & 3) * 2;

    if (MODE == 0) {
        #pragma unroll
        for (int mt = 0; mt < 4; mt++)
            #pragma unroll
            for (int h = 0; h < 2; h++) {
                int ri = (mt*16 + qr + 8*h) & 63;
                float sc = wm ? s1[ri] : s0[ri];
                float bi = wm ? b1v[ri] : b0v[ri];
                #pragma unroll
                for (int nt = 0; nt < 8; nt++) {
                    acc[mt][nt][2*h]   = fmaf(acc[mt][nt][2*h],   sc, bi);
                    acc[mt][nt][2*h+1] = fmaf(acc[mt][nt][2*h+1], sc, bi);
                }
            }
        float inv[8][2];
        #pragma unroll
        for (int nt = 0; nt < 8; nt++)
            #pragma unroll
            for (int j = 0; j < 2; j++) {
                float ss = 0.f;
                #pragma unroll
                for (int mt = 0; mt < 4; mt++)
                    ss += acc[mt][nt][j]*acc[mt][nt][j] + acc[mt][nt][2+j]*acc[mt][nt][2+j];
                ss += __shfl_xor_sync(0xffffffffu, ss, 4);
                ss += __shfl_xor_sync(0xffffffffu, ss, 8);
                ss += __shfl_xor_sync(0xffffffffu, ss, 16);
                inv[nt][j] = 1.f / fmaxf(sqrtf(ss), 1e-12f);
            }
        if (wm == 0) {
            // Q rows: fp32 (fuse consumes them)
            float* dst = g_Q + (size_t)bidx * CKD * NPIX;
            #pragma unroll
            for (int mt = 0; mt < 4; mt++)
                #pragma unroll
                for (int h = 0; h < 2; h++) {
                    int ch = (mt*16 + qr + 8*h) & 63;
                    #pragma unroll
                    for (int nt = 0; nt < 8; nt++) {
                        int col = n0 + wn*64 + nt*8 + qc;
                        float2 o = make_float2(acc[mt][nt][2*h]   * inv[nt][0],
                                               acc[mt][nt][2*h+1] * inv[nt][1]);
                        *reinterpret_cast<float2*>(&dst[(size_t)ch * NPIX + col]) = o;
                    }
                }
        } else {
            // K rows: split fp16 hi/lo for sim_mma
            #pragma unroll
            for (int mt = 0; mt < 4; mt++)
                #pragma unroll
                for (int h = 0; h < 2; h++) {
                    int ch = (mt*16 + qr + 8*h) & 63;
                    h16* kd = g_Kh + ((size_t)bidx * CKD + ch) * 2 * NPIX;
                    #pragma unroll
                    for (int nt = 0; nt < 8; nt++) {
                        int col = n0 + wn*64 + nt*8 + qc;
                        float v0 = acc[mt][nt][2*h]   * inv[nt][0];
                        float v1 = acc[mt][nt][2*h+1] * inv[nt][1];
                        *reinterpret_cast<unsigned*>(&kd[col]) = pk2h(v0, v1);
                        *reinterpret_cast<unsigned*>(&kd[NPIX + col]) =
                            pk2h(v0 - hhi_f(v0), v1 - hhi_f(v1));
                    }
                }
        }
    } else if (MODE == 1) {
        // V: relu(affine) -> split fp16 hi/lo
        #pragma unroll
        for (int mt = 0; mt < 4; mt++)
            #pragma unroll
            for (int h = 0; h < 2; h++) {
                int row = row0 + wm*64 + mt*16 + qr + 8*h;
                float sc = s0[row], bi = b0v[row];
                h16* vd = g_Vh + ((size_t)bidx * CIN + row) * 2 * NPIX;
                #pragma unroll
                for (int nt = 0; nt < 8; nt++) {
                    int col = n0 + wn*64 + nt*8 + qc;
                    float v0 = fmaxf(fmaf(acc[mt][nt][2*h],   sc, bi), 0.f);
                    float v1 = fmaxf(fmaf(acc[mt][nt][2*h+1], sc, bi), 0.f);
                    *reinterpret_cast<unsigned*>(&vd[col]) = pk2h(v0, v1);
                    *reinterpret_cast<unsigned*>(&vd[NPIX + col]) =
                        pk2h(v0 - hhi_f(v0), v1 - hhi_f(v1));
                }
            }
    } else {
        #pragma unroll
        for (int mt = 0; mt < 4; mt++)
            #pragma unroll
            for (int h = 0; h < 2; h++) {
                int row = row0 + wm*64 + mt*16 + qr + 8*h;
                float sc = s0[row], bi = b0v[row];
                #pragma unroll
                for (int nt = 0; nt < 8; nt++) {
                    int col = n0 + wn*64 + nt*8 + qc;
                    float2 o;
                    o.x = fmaxf(fmaf(acc[mt][nt][2*h],   sc, bi), 0.f);
                    o.y = fmaxf(fmaf(acc[mt][nt][2*h+1], sc, bi), 0.f);
                    *reinterpret_cast<float2*>(
                        &outp[((size_t)bidx * COUT + row) * NPIX + col]) = o;
                }
            }
    }
}

// ---------------- sim via mma: simP[c][k] += Vh[c][n] * Kh[k][n], 3-pass ----------
// CTA 128(M=c) x 64(N=k), split-K over 4 n-chunks of 1024.
__global__ __launch_bounds__(128) void sim_mma()
{
    __shared__ __align__(16) h16 sm[2][4][128][24];   // Ahi,Alo,Bhi,Blo = 48KB
    const int b = blockIdx.z, chunk = blockIdx.y, c0 = blockIdx.x * 128;
    const int t = threadIdx.x;
    const int lane = t & 31, w = t >> 5, wm = w >> 1, wn = w & 1;

    float acc[4][4][4];
    #pragma unroll
    for (int i = 0; i < 4; i++)
        #pragma unroll
        for (int j = 0; j < 4; j++)
            #pragma unroll
            for (int c = 0; c < 4; c++) acc[i][j][c] = 0.f;

    const h16* aSrc = g_Vh + ((size_t)b * CIN + c0 + t) * 2 * NPIX + chunk * 1024;
    const h16* bSrc = g_Kh + ((size_t)b * CKD + (t & 63)) * 2 * NPIX + chunk * 1024;

    auto load = [&](int st, int kc) {
        cpa16(&sm[st][0][t][0], aSrc + kc);
        cpa16(&sm[st][0][t][8], aSrc + kc + 8);
        cpa16(&sm[st][1][t][0], aSrc + NPIX + kc);
        cpa16(&sm[st][1][t][8], aSrc + NPIX + kc + 8);
        if (t < 64) {
            cpa16(&sm[st][2][t][0], bSrc + kc);
            cpa16(&sm[st][2][t][8], bSrc + kc + 8);
            cpa16(&sm[st][3][t][0], bSrc + NPIX + kc);
            cpa16(&sm[st][3][t][8], bSrc + NPIX + kc + 8);
        }
        cp_commit();
    };

    const int ar  = wm*64 + (lane & 15);
    const int acl = (lane >> 4) * 8;
    const int br  = wn*32 + ((lane >> 4) << 3) + (lane & 7);
    const int bcl = ((lane >> 3) & 1) * 8;

    load(0, 0);
    #pragma unroll 1
    for (int kt = 0; kt < 64; kt++) {
        int cur = kt & 1;
        if (kt + 1 < 64) { load(cur ^ 1, (kt+1)*16); cp_wait1(); }
        else              cp_wait0();
        __syncthreads();

        unsigned ah[4][4], al[4][4], bh[4][2], bl[4][2];
        #pragma unroll
        for (int mt = 0; mt < 4; mt++) ldm4(ah[mt], &sm[cur][0][ar + mt*16][acl]);
        #pragma unroll
        for (int mt = 0; mt < 4; mt++) ldm4(al[mt], &sm[cur][1][ar + mt*16][acl]);
        #pragma unroll
        for (int g = 0; g < 2; g++) ldm4(&bh[2*g][0], &sm[cur][2][br + g*16][bcl]);
        #pragma unroll
        for (int g = 0; g < 2; g++) ldm4(&bl[2*g][0], &sm[cur][3][br + g*16][bcl]);
        #pragma unroll
        for (int mt = 0; mt < 4; mt++)
            #pragma unroll
            for (int nt = 0; nt < 4; nt++)
                mma16816h(acc[mt][nt], ah[mt], bh[nt]);        // hi*hi
        #pragma unroll
        for (int mt = 0; mt < 4; mt++)
            #pragma unroll
            for (int nt = 0; nt < 4; nt++)
                mma16816h(acc[mt][nt], al[mt], bh[nt]);        // lo*hi
        #pragma unroll
        for (int mt = 0; mt < 4; mt++)
            #pragma unroll
            for (int nt = 0; nt < 4; nt++)
                mma16816h(acc[mt][nt], ah[mt], bl[nt]);        // hi*lo
        __syncthreads();
    }

    const int qr = lane >> 2, qc = (lane & 3) * 2;
    float* pb = g_simP + (size_t)(b*4 + chunk) * CIN * CKD;
    #pragma unroll
    for (int mt = 0; mt < 4; mt++)
        #pragma unroll
        for (int h = 0; h < 2; h++) {
            int row = c0 + wm*64 + mt*16 + qr + 8*h;
            #pragma unroll
            for (int nt = 0; nt < 4; nt++) {
                int col = wn*32 + nt*8 + qc;
                float2 o = make_float2(acc[mt][nt][2*h], acc[mt][nt][2*h+1]);
                *reinterpret_cast<float2*>(&pb[(size_t)row * CKD + col]) = o;
            }
        }
}

__global__ __launch_bounds__(256) void sim_reduce()
{
    int idx = blockIdx.x * 256 + threadIdx.x;
    if (idx >= BB * CIN * CKD) return;
    int b = idx / (CIN * CKD);
    int rem = idx - b * CIN * CKD;
    float s = 0.f;
    #pragma unroll
    for (int p = 0; p < 4; p++)
        s += g_simP[(size_t)(b*4 + p) * CIN * CKD + rem];
    g_simT[idx] = s;
}

__global__ __launch_bounds__(256) void wos_kernel(const float* __restrict__ wo)
{
    __shared__ __align__(16) float As[16][64];
    __shared__ __align__(16) float Bs[16][64];
    const int b = blockIdx.y;
    const int row0 = blockIdx.x * 64;
    const float* ST = g_simT + (size_t)b * CIN * CKD;
    const int t = threadIdx.x;
    const int tr = t >> 4, tc = t & 15;
    float acc[4][4];
    #pragma unroll
    for (int i = 0; i < 4; i++)
        #pragma unroll
        for (int j = 0; j < 4; j++) acc[i][j] = 0.f;

    for (int kb = 0; kb < CIN; kb += 16) {
        {
            int r  = t >> 2;
            int k4 = (t & 3) << 2;
            float4 va = *reinterpret_cast<const float4*>(wo + (size_t)(row0 + r) * CIN + kb + k4);
            As[k4+0][r] = va.x; As[k4+1][r] = va.y; As[k4+2][r] = va.z; As[k4+3][r] = va.w;
            int kk = t >> 4;
            int n4 = (t & 15) << 2;
            *reinterpret_cast<float4*>(&Bs[kk][n4]) =
                *reinterpret_cast<const float4*>(ST + (size_t)(kb + kk) * CKD + n4);
        }
        __syncthreads();
        #pragma unroll
        for (int kk = 0; kk < 16; kk++) {
            float4 a = *reinterpret_cast<float4*>(&As[kk][tr*4]);
            float4 bbv = *reinterpret_cast<float4*>(&Bs[kk][tc*4]);
            float av[4] = {a.x,a.y,a.z,a.w};
            float bv[4] = {bbv.x,bbv.y,bbv.z,bbv.w};
            #pragma unroll
            for (int i = 0; i < 4; i++)
                #pragma unroll
                for (int j = 0; j < 4; j++)
                    acc[i][j] = fmaf(av[i], bv[j], acc[i][j]);
        }
        __syncthreads();
    }
    #pragma unroll
    for (int i = 0; i < 4; i++) {
        int o = row0 + tr * 4 + i;
        float4 ov = make_float4(acc[i][0], acc[i][1], acc[i][2], acc[i][3]);
        *reinterpret_cast<float4*>(g_Wos + (size_t)b * CIN * CKD + (size_t)o * CKD + tc*4) = ov;
    }
}

// ---------------- zero fuseT borders ----------------
__global__ __launch_bounds__(256) void zero_borderT()
{
    int idx = blockIdx.x * 256 + threadIdx.x;
    if (idx >= BB * 260 * 64) return;
    int c16 = idx & 63;
    int r = idx >> 6;
    int b = r / 260, p = r - b * 260;
    int y, x;
    if (p < 66)       { y = 0;  x = p; }
    else if (p < 132) { y = 65; x = p - 66; }
    else if (p < 196) { y = p - 132 + 1; x = 0; }
    else              { y = p - 196 + 1; x = 65; }
    uint4* d = reinterpret_cast<uint4*>(g_fuseT + (((size_t)b*66 + y)*66 + x)*512);
    d[c16] = make_uint4(0, 0, 0, 0);
}

// ---------------- fuse = relu(affine(Wos @ Q)) + x + up -> fuseT (fp16) ----------
__global__ __launch_bounds__(256) void fuse_kernel(
    const float* __restrict__ x, const float* __restrict__ up,
    const float* __restrict__ so, const float* __restrict__ bo)
{
    __shared__ __align__(16) float As[16][128];
    __shared__ __align__(16) float Bs[16][64];
    __shared__ float Cs[128][65];
    const int b = blockIdx.z;
    const int row0 = blockIdx.y * 128;
    const int h = blockIdx.x;
    const int col0 = h * 64;
    const float* Wos = g_Wos + (size_t)b * CIN * CKD;
    const float* Qm  = g_Q   + (size_t)b * CKD * NPIX;
    const int t = threadIdx.x;
    const int tr = t >> 4, tc = t & 15;
    float acc[8][4];
    #pragma unroll
    for (int i = 0; i < 8; i++)
        #pragma unroll
        for (int j = 0; j < 4; j++) acc[i][j] = 0.f;

    for (int kb = 0; kb < CKD; kb += 16) {
        #pragma unroll
        for (int q = 0; q < 2; q++) {
            int idx = t * 2 + q;
            int row = idx >> 2;
            int k4  = (idx & 3) << 2;
            float4 v4 = *reinterpret_cast<const float4*>(Wos + (size_t)(row0 + row) * CKD + kb + k4);
            As[k4+0][row] = v4.x; As[k4+1][row] = v4.y;
            As[k4+2][row] = v4.z; As[k4+3][row] = v4.w;
        }
        {
            int kk = t >> 4;
            int n4 = (t & 15) << 2;
            *reinterpret_cast<float4*>(&Bs[kk][n4]) =
                *reinterpret_cast<const float4*>(Qm + (size_t)(kb + kk) * NPIX + col0 + n4);
        }
        __syncthreads();
        #pragma unroll
        for (int kk = 0; kk < 16; kk++) {
            float4 a0 = *reinterpret_cast<float4*>(&As[kk][tr*8]);
            float4 a1 = *reinterpret_cast<float4*>(&As[kk][tr*8+4]);
            float4 b0 = *reinterpret_cast<float4*>(&Bs[kk][tc*4]);
            float av[8] = {a0.x,a0.y,a0.z,a0.w,a1.x,a1.y,a1.z,a1.w};
            float bv[4] = {b0.x,b0.y,b0.z,b0.w};
            #pragma unroll
            for (int i = 0; i < 8; i++)
                #pragma unroll
                for (int j = 0; j < 4; j++)
                    acc[i][j] = fmaf(av[i], bv[j], acc[i][j]);
        }
        __syncthreads();
    }
    #pragma unroll
    for (int i = 0; i < 8; i++) {
        int row = row0 + tr * 8 + i;
        float s = so[row], bi = bo[row];
        size_t xoff = (size_t)b * CIN * NPIX + (size_t)row * NPIX + col0 + tc*4;
        float4 xv = *reinterpret_cast<const float4*>(x + xoff);
        float4 uv = *reinterpret_cast<const float4*>(up + xoff);
        Cs[tr*8+i][tc*4+0] = fmaxf(fmaf(acc[i][0], s, bi), 0.f) + xv.x + uv.x;
        Cs[tr*8+i][tc*4+1] = fmaxf(fmaf(acc[i][1], s, bi), 0.f) + xv.y + uv.y;
        Cs[tr*8+i][tc*4+2] = fmaxf(fmaf(acc[i][2], s, bi), 0.f) + xv.z + uv.z;
        Cs[tr*8+i][tc*4+3] = fmaxf(fmaf(acc[i][3], s, bi), 0.f) + xv.w + uv.w;
    }
    __syncthreads();
    #pragma unroll
    for (int it = 0; it < 4; it++) {
        int task = it * 256 + t;
        int pix = task >> 4, cg = task & 15;
        float f[8];
        #pragma unroll
        for (int j2 = 0; j2 < 8; j2++) f[j2] = Cs[cg*8 + j2][pix];
        unsigned hh[4];
        pack8h(f, hh);
        h16* d = g_fuseT + (((size_t)b*66 + h + 1)*66 + pix + 1)*512 + row0 + cg*8;
        *reinterpret_cast<uint4*>(d) = make_uint4(hh[0], hh[1], hh[2], hh[3]);
    }
}

// ================= launch =================
extern "C" void kernel_launch(void* const* d_in, const int* in_sizes, int n_in,
                              void* d_out, int out_size)
{
    const float* x  = (const float*)d_in[0];
    const float* up = (const float*)d_in[1];
    const float* wq = (const float*)d_in[2];
    const float* sq = (const float*)d_in[3];
    const float* bq = (const float*)d_in[4];
    const float* wk = (const float*)d_in[5];
    const float* sk = (const float*)d_in[6];
    const float* bk = (const float*)d_in[7];
    const float* wv = (const float*)d_in[8];
    const float* sv = (const float*)d_in[9];
    const float* bv = (const float*)d_in[10];
    const float* wo = (const float*)d_in[11];
    const float* so = (const float*)d_in[12];
    const float* bo = (const float*)d_in[13];
    const float* ws = (const float*)d_in[14];
    const float* ss = (const float*)d_in[15];
    const float* bs = (const float*)d_in[16];
    float* out = (float*)d_out;

    prep_split<<<16, 256>>>(wq, 64, 0);
    prep_split<<<16, 256>>>(wk, 64, 1);
    prep_split<<<128, 256>>>(wv, 512, 2);
    prep_wconv<<<288, 256>>>(ws);
    xt_kernel<<<dim3(64, 16, 8), 256>>>(x);
    mma_gemm<0><<<dim3(32, 1, 8), 128>>>(sq, bq, sk, bk, nullptr);
    mma_gemm<1><<<dim3(32, 4, 8), 128>>>(sv, bv, nullptr, nullptr, nullptr);
    sim_mma<<<dim3(4, 4, 8), 128>>>();
    sim_reduce<<<(BB * CIN * CKD + 255) / 256, 256>>>();
    wos_kernel<<<dim3(8, 8), 256>>>(wo);
    zero_borderT<<<(BB * 260 * 64 + 255) / 256, 256>>>();
    fuse_kernel<<<dim3(64, 4, 8), 256>>>(x, up, so, bo);
    mma_gemm<2><<<dim3(32, 1, 8), 128>>>(ss, bs, nullptr, nullptr, out);
}

// round 9
// speedup vs baseline: 3.0426x; 1.0032x over previous
#include <cuda_runtime.h>
#include <cuda_fp16.h>
#include <math.h>

#define BB 8
#define CIN 512
#define NPIX 4096
#define CKD 64
#define COUT 128
#define KCONV 4608

typedef __half h16;

// ---------------- device scratch ----------------
__device__ __align__(16) h16 g_XT[(size_t)BB*NPIX*512];        // [b][n][c512] fp16
__device__ __align__(16) h16 g_fuseT[(size_t)BB*66*66*512];    // [b][y][x][c512] fp16
__device__ __align__(16) h16 g_Wqk[128*1024];                  // [m][hi512|lo512]
__device__ __align__(16) h16 g_Wv[512*1024];
__device__ __align__(16) h16 g_Wc[128*2*KCONV];                // permuted k'=(r9*512+ic), hi|lo
__device__ __align__(16) h16 g_Vh[(size_t)BB*CIN*2*NPIX];      // [b][c][hi|lo][n]
__device__ __align__(16) h16 g_Kh[(size_t)BB*CKD*2*NPIX];      // [b][k][hi|lo][n]
__device__ __align__(16) h16 g_QT[(size_t)BB*NPIX*128];        // [b][n][hi64|lo64]
__device__ __align__(16) h16 g_WosH[BB*CIN*128];               // [b][o][hi64|lo64]
__device__ float g_simP[BB*4*CIN*CKD];
__device__ float g_simT[BB*CIN*CKD];

// ---------------- helpers ----------------
__device__ __forceinline__ unsigned pk2h(float a, float b) {
    __half2 h = __floats2half2_rn(a, b);
    return *reinterpret_cast<unsigned*>(&h);
}
__device__ __forceinline__ float hhi_f(float x) { return __half2float(__float2half_rn(x)); }
__device__ __forceinline__ void split8h(const float* f, unsigned* hi, unsigned* lo) {
    #pragma unroll
    for (int i = 0; i < 4; i++) {
        float f0 = f[2*i], f1 = f[2*i+1];
        hi[i] = pk2h(f0, f1);
        lo[i] = pk2h(f0 - hhi_f(f0), f1 - hhi_f(f1));
    }
}
__device__ __forceinline__ void pack8h(const float* f, unsigned* hi) {
    #pragma unroll
    for (int i = 0; i < 4; i++) hi[i] = pk2h(f[2*i], f[2*i+1]);
}
__device__ __forceinline__ unsigned su32(const void* p) {
    return (unsigned)__cvta_generic_to_shared(p);
}
__device__ __forceinline__ void cpa16(void* sdst, const void* gsrc) {
    asm volatile("cp.async.cg.shared.global [%0], [%1], 16;" :: "r"(su32(sdst)), "l"(gsrc));
}
__device__ __forceinline__ void cp_commit() { asm volatile("cp.async.commit_group;" ::: "memory"); }
__device__ __forceinline__ void cp_wait1()  { asm volatile("cp.async.wait_group 1;" ::: "memory"); }
__device__ __forceinline__ void cp_wait0()  { asm volatile("cp.async.wait_group 0;" ::: "memory"); }
__device__ __forceinline__ void mma16816h(float* d, const unsigned* a, const unsigned* b) {
    asm("mma.sync.aligned.m16n8k16.row.col.f32.f16.f16.f32 "
        "{%0,%1,%2,%3},{%4,%5,%6,%7},{%8,%9},{%0,%1,%2,%3};"
        : "+f"(d[0]), "+f"(d[1]), "+f"(d[2]), "+f"(d[3])
        : "r"(a[0]), "r"(a[1]), "r"(a[2]), "r"(a[3]), "r"(b[0]), "r"(b[1]));
}
__device__ __forceinline__ void ldm4(unsigned* r, const h16* p) {
    asm volatile("ldmatrix.sync.aligned.m8n8.x4.shared.b16 {%0,%1,%2,%3}, [%4];"
        : "=r"(r[0]), "=r"(r[1]), "=r"(r[2]), "=r"(r[3]) : "r"(su32(p)));
}

// ---------------- prep: split fp32 weights to hi/lo fp16 ----------------
__global__ __launch_bounds__(256) void prep_split(const float* __restrict__ src,
                                                  int rows, int which)
{
    h16* dst = (which == 0) ? g_Wqk : (which == 1) ? (g_Wqk + 64*1024) : g_Wv;
    int idx = blockIdx.x * 256 + threadIdx.x;
    if (idx >= rows * 64) return;
    int m = idx >> 6, kg = idx & 63;
    float f[8];
    *reinterpret_cast<float4*>(f)     = *reinterpret_cast<const float4*>(src + (size_t)m*512 + kg*8);
    *reinterpret_cast<float4*>(f + 4) = *reinterpret_cast<const float4*>(src + (size_t)m*512 + kg*8 + 4);
    unsigned hi[4], lo[4];
    split8h(f, hi, lo);
    h16* d = dst + (size_t)m * 1024 + kg*8;
    *reinterpret_cast<uint4*>(d)       = make_uint4(hi[0], hi[1], hi[2], hi[3]);
    *reinterpret_cast<uint4*>(d + 512) = make_uint4(lo[0], lo[1], lo[2], lo[3]);
}

// ---------------- prep: conv weights permute + split ----------------
__global__ __launch_bounds__(256) void prep_wconv(const float* __restrict__ ws)
{
    int idx = blockIdx.x * 256 + threadIdx.x;
    if (idx >= 128 * 576) return;
    int oc = idx / 576, kg = idx - oc * 576;
    int kp0 = kg * 8;
    int r9 = kp0 >> 9, ic = kp0 & 511;
    float f[8];
    #pragma unroll
    for (int j = 0; j < 8; j++)
        f[j] = ws[(size_t)oc * KCONV + (ic + j) * 9 + r9];
    unsigned hi[4], lo[4];
    split8h(f, hi, lo);
    h16* d = g_Wc + (size_t)oc * 2 * KCONV + kp0;
    *reinterpret_cast<uint4*>(d)         = make_uint4(hi[0], hi[1], hi[2], hi[3]);
    *reinterpret_cast<uint4*>(d + KCONV) = make_uint4(lo[0], lo[1], lo[2], lo[3]);
}

// ---------------- xt: x[b][c][n] -> XT[b][n][c] fp16 ----------------
__global__ __launch_bounds__(256) void xt_kernel(const float* __restrict__ x)
{
    __shared__ float tile[32][65];
    const int b = blockIdx.z, c0 = blockIdx.y * 32, n0 = blockIdx.x * 64;
    const int t = threadIdx.x;
    {
        int r = t >> 3, nq = (t & 7) * 8;
        const float* src = x + ((size_t)b * CIN + c0 + r) * NPIX + n0 + nq;
        float4 a = *reinterpret_cast<const float4*>(src);
        float4 c = *reinterpret_cast<const float4*>(src + 4);
        tile[r][nq+0]=a.x; tile[r][nq+1]=a.y; tile[r][nq+2]=a.z; tile[r][nq+3]=a.w;
        tile[r][nq+4]=c.x; tile[r][nq+5]=c.y; tile[r][nq+6]=c.z; tile[r][nq+7]=c.w;
    }
    __syncthreads();
    {
        int xc = t & 63, grp = t >> 6;
        float f[8];
        #pragma unroll
        for (int i = 0; i < 8; i++) f[i] = tile[grp*8 + i][xc];
        unsigned hh[4];
        pack8h(f, hh);
        h16* d = g_XT + ((size_t)b * NPIX + n0 + xc) * 512 + c0 + grp*8;
        *reinterpret_cast<uint4*>(d) = make_uint4(hh[0], hh[1], hh[2], hh[3]);
    }
}

// ---------------- big GEMMs: 2-pass fp16, ldmatrix, 64x64 warp tiles ----------------
template<int MODE>
__global__ __launch_bounds__(128) void mma_gemm(
    const float* __restrict__ s0, const float* __restrict__ b0v,
    const float* __restrict__ s1, const float* __restrict__ b1v,
    float* __restrict__ outp)
{
    constexpr int KD = (MODE == 2) ? KCONV : 512;
    constexpr int NSTEP = KD / 16;
    __shared__ __align__(16) h16 sm[2][3][128][24];   // 36KB
    const int bidx = blockIdx.z;
    const int n0 = blockIdx.x * 128;
    const int row0 = blockIdx.y * 128;
    const int t = threadIdx.x;
    const int lane = t & 31, w = t >> 5, wm = w >> 1, wn = w & 1;

    float acc[4][8][4];
    #pragma unroll
    for (int i = 0; i < 4; i++)
        #pragma unroll
        for (int j = 0; j < 8; j++)
            #pragma unroll
            for (int c = 0; c < 4; c++) acc[i][j][c] = 0.f;

    const h16* W = (MODE == 0) ? g_Wqk : (MODE == 1) ? g_Wv : g_Wc;
    const h16* aSrc = W + (size_t)(row0 + t) * (2*KD);
    const h16* bSrcX = g_XT + ((size_t)bidx * NPIX + n0 + t) * 512;
    int yi = 0, xi = 0;
    if (MODE == 2) { int p = n0 + t; yi = p >> 6; xi = p & 63; }

    auto load = [&](int st, int kc) {
        cpa16(&sm[st][0][t][0], aSrc + kc);
        cpa16(&sm[st][0][t][8], aSrc + kc + 8);
        cpa16(&sm[st][1][t][0], aSrc + KD + kc);
        cpa16(&sm[st][1][t][8], aSrc + KD + kc + 8);
        const h16* bp;
        if (MODE == 2) {
            int r9 = kc >> 9, kin = kc & 511;
            int dy = r9 / 3, dx = r9 - dy*3;
            bp = g_fuseT + (((size_t)bidx*66 + yi + dy)*66 + xi + dx)*512 + kin;
        } else {
            bp = bSrcX + kc;
        }
        cpa16(&sm[st][2][t][0], bp);
        cpa16(&sm[st][2][t][8], bp + 8);
        cp_commit();
    };

    const int ar  = wm*64 + (lane & 15);
    const int acl = (lane >> 4) * 8;
    const int br  = wn*64 + ((lane >> 4) << 3) + (lane & 7);
    const int bcl = ((lane >> 3) & 1) * 8;

    load(0, 0);
    #pragma unroll 1
    for (int kt = 0; kt < NSTEP; kt++) {
        int cur = kt & 1;
        if (kt + 1 < NSTEP) { load(cur ^ 1, (kt+1)*16); cp_wait1(); }
        else                 cp_wait0();
        __syncthreads();

        unsigned ah[4][4], al[4][4], bfr[8][2];
        #pragma unroll
        for (int mt = 0; mt < 4; mt++) ldm4(ah[mt], &sm[cur][0][ar + mt*16][acl]);
        #pragma unroll
        for (int mt = 0; mt < 4; mt++) ldm4(al[mt], &sm[cur][1][ar + mt*16][acl]);
        #pragma unroll
        for (int g = 0; g < 4; g++) ldm4(&bfr[2*g][0], &sm[cur][2][br + g*16][bcl]);
        #pragma unroll
        for (int mt = 0; mt < 4; mt++)
            #pragma unroll
            for (int nt = 0; nt < 8; nt++)
                mma16816h(acc[mt][nt], ah[mt], bfr[nt]);       // hi*B
        #pragma unroll
        for (int mt = 0; mt < 4; mt++)
            #pragma unroll
            for (int nt = 0; nt < 8; nt++)
                mma16816h(acc[mt][nt], al[mt], bfr[nt]);       // lo*B
        __syncthreads();
    }

    const int qr = lane >> 2, qc = (lane & 3) * 2;

    if (MODE == 0) {
        #pragma unroll
        for (int mt = 0; mt < 4; mt++)
            #pragma unroll
            for (int h = 0; h < 2; h++) {
                int ri = (mt*16 + qr + 8*h) & 63;
                float sc = wm ? s1[ri] : s0[ri];
                float bi = wm ? b1v[ri] : b0v[ri];
                #pragma unroll
                for (int nt = 0; nt < 8; nt++) {
                    acc[mt][nt][2*h]   = fmaf(acc[mt][nt][2*h],   sc, bi);
                    acc[mt][nt][2*h+1] = fmaf(acc[mt][nt][2*h+1], sc, bi);
                }
            }
        float inv[8][2];
        #pragma unroll
        for (int nt = 0; nt < 8; nt++)
            #pragma unroll
            for (int j = 0; j < 2; j++) {
                float ss = 0.f;
                #pragma unroll
                for (int mt = 0; mt < 4; mt++)
                    ss += acc[mt][nt][j]*acc[mt][nt][j] + acc[mt][nt][2+j]*acc[mt][nt][2+j];
                ss += __shfl_xor_sync(0xffffffffu, ss, 4);
                ss += __shfl_xor_sync(0xffffffffu, ss, 8);
                ss += __shfl_xor_sync(0xffffffffu, ss, 16);
                inv[nt][j] = 1.f / fmaxf(sqrtf(ss), 1e-12f);
            }
        if (wm == 0) {
            // Q rows: pixel-major split fp16 (fuse_mma consumes)
            h16* qd = g_QT + (size_t)bidx * NPIX * 128;
            #pragma unroll
            for (int mt = 0; mt < 4; mt++)
                #pragma unroll
                for (int h = 0; h < 2; h++) {
                    int ch = (mt*16 + qr + 8*h) & 63;
                    #pragma unroll
                    for (int nt = 0; nt < 8; nt++) {
                        int col = n0 + wn*64 + nt*8 + qc;
                        float v0 = acc[mt][nt][2*h]   * inv[nt][0];
                        float v1 = acc[mt][nt][2*h+1] * inv[nt][1];
                        qd[(size_t)col*128 + ch]          = __float2half_rn(v0);
                        qd[(size_t)col*128 + 64 + ch]     = __float2half_rn(v0 - hhi_f(v0));
                        qd[(size_t)(col+1)*128 + ch]      = __float2half_rn(v1);
                        qd[(size_t)(col+1)*128 + 64 + ch] = __float2half_rn(v1 - hhi_f(v1));
                    }
                }
        } else {
            // K rows: split fp16 hi/lo for sim_mma
            #pragma unroll
            for (int mt = 0; mt < 4; mt++)
                #pragma unroll
                for (int h = 0; h < 2; h++) {
                    int ch = (mt*16 + qr + 8*h) & 63;
                    h16* kd = g_Kh + ((size_t)bidx * CKD + ch) * 2 * NPIX;
                    #pragma unroll
                    for (int nt = 0; nt < 8; nt++) {
                        int col = n0 + wn*64 + nt*8 + qc;
                        float v0 = acc[mt][nt][2*h]   * inv[nt][0];
                        float v1 = acc[mt][nt][2*h+1] * inv[nt][1];
                        *reinterpret_cast<unsigned*>(&kd[col]) = pk2h(v0, v1);
                        *reinterpret_cast<unsigned*>(&kd[NPIX + col]) =
                            pk2h(v0 - hhi_f(v0), v1 - hhi_f(v1));
                    }
                }
        }
    } else if (MODE == 1) {
        // V: relu(affine) -> split fp16 hi/lo
        #pragma unroll
        for (int mt = 0; mt < 4; mt++)
            #pragma unroll
            for (int h = 0; h < 2; h++) {
                int row = row0 + wm*64 + mt*16 + qr + 8*h;
                float sc = s0[row], bi = b0v[row];
                h16* vd = g_Vh + ((size_t)bidx * CIN + row) * 2 * NPIX;
                #pragma unroll
                for (int nt = 0; nt < 8; nt++) {
                    int col = n0 + wn*64 + nt*8 + qc;
                    float v0 = fmaxf(fmaf(acc[mt][nt][2*h],   sc, bi), 0.f);
                    float v1 = fmaxf(fmaf(acc[mt][nt][2*h+1], sc, bi), 0.f);
                    *reinterpret_cast<unsigned*>(&vd[col]) = pk2h(v0, v1);
                    *reinterpret_cast<unsigned*>(&vd[NPIX + col]) =
                        pk2h(v0 - hhi_f(v0), v1 - hhi_f(v1));
                }
            }
    } else {
        #pragma unroll
        for (int mt = 0; mt < 4; mt++)
            #pragma unroll
            for (int h = 0; h < 2; h++) {
                int row = row0 + wm*64 + mt*16 + qr + 8*h;
                float sc = s0[row], bi = b0v[row];
                #pragma unroll
                for (int nt = 0; nt < 8; nt++) {
                    int col = n0 + wn*64 + nt*8 + qc;
                    float2 o;
                    o.x = fmaxf(fmaf(acc[mt][nt][2*h],   sc, bi), 0.f);
                    o.y = fmaxf(fmaf(acc[mt][nt][2*h+1], sc, bi), 0.f);
                    *reinterpret_cast<float2*>(
                        &outp[((size_t)bidx * COUT + row) * NPIX + col]) = o;
                }
            }
    }
}

// ---------------- sim via mma: simP[c][k] += Vh[c][n] * Kh[k][n], 3-pass ----------
__global__ __launch_bounds__(128) void sim_mma()
{
    __shared__ __align__(16) h16 sm[2][4][128][24];   // 48KB
    const int b = blockIdx.z, chunk = blockIdx.y, c0 = blockIdx.x * 128;
    const int t = threadIdx.x;
    const int lane = t & 31, w = t >> 5, wm = w >> 1, wn = w & 1;

    float acc[4][4][4];
    #pragma unroll
    for (int i = 0; i < 4; i++)
        #pragma unroll
        for (int j = 0; j < 4; j++)
            #pragma unroll
            for (int c = 0; c < 4; c++) acc[i][j][c] = 0.f;

    const h16* aSrc = g_Vh + ((size_t)b * CIN + c0 + t) * 2 * NPIX + chunk * 1024;
    const h16* bSrc = g_Kh + ((size_t)b * CKD + (t & 63)) * 2 * NPIX + chunk * 1024;

    auto load = [&](int st, int kc) {
        cpa16(&sm[st][0][t][0], aSrc + kc);
        cpa16(&sm[st][0][t][8], aSrc + kc + 8);
        cpa16(&sm[st][1][t][0], aSrc + NPIX + kc);
        cpa16(&sm[st][1][t][8], aSrc + NPIX + kc + 8);
        if (t < 64) {
            cpa16(&sm[st][2][t][0], bSrc + kc);
            cpa16(&sm[st][2][t][8], bSrc + kc + 8);
            cpa16(&sm[st][3][t][0], bSrc + NPIX + kc);
            cpa16(&sm[st][3][t][8], bSrc + NPIX + kc + 8);
        }
        cp_commit();
    };

    const int ar  = wm*64 + (lane & 15);
    const int acl = (lane >> 4) * 8;
    const int br  = wn*32 + ((lane >> 4) << 3) + (lane & 7);
    const int bcl = ((lane >> 3) & 1) * 8;

    load(0, 0);
    #pragma unroll 1
    for (int kt = 0; kt < 64; kt++) {
        int cur = kt & 1;
        if (kt + 1 < 64) { load(cur ^ 1, (kt+1)*16); cp_wait1(); }
        else              cp_wait0();
        __syncthreads();

        unsigned ah[4][4], al[4][4], bh[4][2], bl[4][2];
        #pragma unroll
        for (int mt = 0; mt < 4; mt++) ldm4(ah[mt], &sm[cur][0][ar + mt*16][acl]);
        #pragma unroll
        for (int mt = 0; mt < 4; mt++) ldm4(al[mt], &sm[cur][1][ar + mt*16][acl]);
        #pragma unroll
        for (int g = 0; g < 2; g++) ldm4(&bh[2*g][0], &sm[cur][2][br + g*16][bcl]);
        #pragma unroll
        for (int g = 0; g < 2; g++) ldm4(&bl[2*g][0], &sm[cur][3][br + g*16][bcl]);
        #pragma unroll
        for (int mt = 0; mt < 4; mt++)
            #pragma unroll
            for (int nt = 0; nt < 4; nt++)
                mma16816h(acc[mt][nt], ah[mt], bh[nt]);
        #pragma unroll
        for (int mt = 0; mt < 4; mt++)
            #pragma unroll
            for (int nt = 0; nt < 4; nt++)
                mma16816h(acc[mt][nt], al[mt], bh[nt]);
        #pragma unroll
        for (int mt = 0; mt < 4; mt++)
            #pragma unroll
            for (int nt = 0; nt < 4; nt++)
                mma16816h(acc[mt][nt], ah[mt], bl[nt]);
        __syncthreads();
    }

    const int qr = lane >> 2, qc = (lane & 3) * 2;
    float* pb = g_simP + (size_t)(b*4 + chunk) * CIN * CKD;
    #pragma unroll
    for (int mt = 0; mt < 4; mt++)
        #pragma unroll
        for (int h = 0; h < 2; h++) {
            int row = c0 + wm*64 + mt*16 + qr + 8*h;
            #pragma unroll
            for (int nt = 0; nt < 4; nt++) {
                int col = wn*32 + nt*8 + qc;
                float2 o = make_float2(acc[mt][nt][2*h], acc[mt][nt][2*h+1]);
                *reinterpret_cast<float2*>(&pb[(size_t)row * CKD + col]) = o;
            }
        }
}

__global__ __launch_bounds__(256) void sim_reduce()
{
    int idx = blockIdx.x * 256 + threadIdx.x;
    if (idx >= BB * CIN * CKD) return;
    int b = idx / (CIN * CKD);
    int rem = idx - b * CIN * CKD;
    float s = 0.f;
    #pragma unroll
    for (int p = 0; p < 4; p++)
        s += g_simP[(size_t)(b*4 + p) * CIN * CKD + rem];
    g_simT[idx] = s;
}

// ---------------- wos: Wo @ simT -> split fp16 [b][o][hi64|lo64] ----------------
__global__ __launch_bounds__(256) void wos_kernel(const float* __restrict__ wo)
{
    __shared__ __align__(16) float As[16][64];
    __shared__ __align__(16) float Bs[16][64];
    const int b = blockIdx.y;
    const int row0 = blockIdx.x * 64;
    const float* ST = g_simT + (size_t)b * CIN * CKD;
    const int t = threadIdx.x;
    const int tr = t >> 4, tc = t & 15;
    float acc[4][4];
    #pragma unroll
    for (int i = 0; i < 4; i++)
        #pragma unroll
        for (int j = 0; j < 4; j++) acc[i][j] = 0.f;

    for (int kb = 0; kb < CIN; kb += 16) {
        {
            int r  = t >> 2;
            int k4 = (t & 3) << 2;
            float4 va = *reinterpret_cast<const float4*>(wo + (size_t)(row0 + r) * CIN + kb + k4);
            As[k4+0][r] = va.x; As[k4+1][r] = va.y; As[k4+2][r] = va.z; As[k4+3][r] = va.w;
            int kk = t >> 4;
            int n4 = (t & 15) << 2;
            *reinterpret_cast<float4*>(&Bs[kk][n4]) =
                *reinterpret_cast<const float4*>(ST + (size_t)(kb + kk) * CKD + n4);
        }
        __syncthreads();
        #pragma unroll
        for (int kk = 0; kk < 16; kk++) {
            float4 a = *reinterpret_cast<float4*>(&As[kk][tr*4]);
            float4 bbv = *reinterpret_cast<float4*>(&Bs[kk][tc*4]);
            float av[4] = {a.x,a.y,a.z,a.w};
            float bv[4] = {bbv.x,bbv.y,bbv.z,bbv.w};
            #pragma unroll
            for (int i = 0; i < 4; i++)
                #pragma unroll
                for (int j = 0; j < 4; j++)
                    acc[i][j] = fmaf(av[i], bv[j], acc[i][j]);
        }
        __syncthreads();
    }
    #pragma unroll
    for (int i = 0; i < 4; i++) {
        int o = row0 + tr * 4 + i;
        float v0 = acc[i][0], v1 = acc[i][1], v2 = acc[i][2], v3 = acc[i][3];
        h16* d = g_WosH + ((size_t)b * CIN + o) * 128 + tc*4;
        *reinterpret_cast<uint2*>(d) =
            make_uint2(pk2h(v0, v1), pk2h(v2, v3));
        *reinterpret_cast<uint2*>(d + 64) =
            make_uint2(pk2h(v0 - hhi_f(v0), v1 - hhi_f(v1)),
                       pk2h(v2 - hhi_f(v2), v3 - hhi_f(v3)));
    }
}

// ---------------- zero fuseT borders ----------------
__global__ __launch_bounds__(256) void zero_borderT()
{
    int idx = blockIdx.x * 256 + threadIdx.x;
    if (idx >= BB * 260 * 64) return;
    int c16 = idx & 63;
    int r = idx >> 6;
    int b = r / 260, p = r - b * 260;
    int y, x;
    if (p < 66)       { y = 0;  x = p; }
    else if (p < 132) { y = 65; x = p - 66; }
    else if (p < 196) { y = p - 132 + 1; x = 0; }
    else              { y = p - 196 + 1; x = 65; }
    uint4* d = reinterpret_cast<uint4*>(g_fuseT + (((size_t)b*66 + y)*66 + x)*512);
    d[c16] = make_uint4(0, 0, 0, 0);
}

// ---------------- fuse via mma: relu(affine(WosH @ QT)) + x + up -> fuseT --------
// CTA 128(c) x 128(n), K=64 (4 k16 steps), 3-pass split fp16.
__global__ __launch_bounds__(128) void fuse_mma(
    const float* __restrict__ x, const float* __restrict__ up,
    const float* __restrict__ so, const float* __restrict__ bo)
{
    __shared__ __align__(16) h16 sm[2][4][128][24];   // 48KB; reused as transpose buf
    const int b = blockIdx.z;
    const int n0 = blockIdx.x * 128;
    const int row0 = blockIdx.y * 128;
    const int t = threadIdx.x;
    const int lane = t & 31, w = t >> 5, wm = w >> 1, wn = w & 1;

    float acc[4][8][4];
    #pragma unroll
    for (int i = 0; i < 4; i++)
        #pragma unroll
        for (int j = 0; j < 8; j++)
            #pragma unroll
            for (int c = 0; c < 4; c++) acc[i][j][c] = 0.f;

    const h16* aSrc = g_WosH + ((size_t)b * CIN + row0 + t) * 128;
    const h16* bSrc = g_QT   + ((size_t)b * NPIX + n0 + t) * 128;

    auto load = [&](int st, int kc) {
        cpa16(&sm[st][0][t][0], aSrc + kc);
        cpa16(&sm[st][0][t][8], aSrc + kc + 8);
        cpa16(&sm[st][1][t][0], aSrc + 64 + kc);
        cpa16(&sm[st][1][t][8], aSrc + 64 + kc + 8);
        cpa16(&sm[st][2][t][0], bSrc + kc);
        cpa16(&sm[st][2][t][8], bSrc + kc + 8);
        cpa16(&sm[st][3][t][0], bSrc + 64 + kc);
        cpa16(&sm[st][3][t][8], bSrc + 64 + kc + 8);
        cp_commit();
    };

    const int ar  = wm*64 + (lane & 15);
    const int acl = (lane >> 4) * 8;
    const int br  = wn*64 + ((lane >> 4) << 3) + (lane & 7);
    const int bcl = ((lane >> 3) & 1) * 8;

    load(0, 0);
    #pragma unroll 1
    for (int kt = 0; kt < 4; kt++) {
        int cur = kt & 1;
        if (kt + 1 < 4) { load(cur ^ 1, (kt+1)*16); cp_wait1(); }
        else             cp_wait0();
        __syncthreads();

        unsigned ah[4][4], al[4][4], bh[8][2], bl[8][2];
        #pragma unroll
        for (int mt = 0; mt < 4; mt++) ldm4(ah[mt], &sm[cur][0][ar + mt*16][acl]);
        #pragma unroll
        for (int mt = 0; mt < 4; mt++) ldm4(al[mt], &sm[cur][1][ar + mt*16][acl]);
        #pragma unroll
        for (int g = 0; g < 4; g++) ldm4(&bh[2*g][0], &sm[cur][2][br + g*16][bcl]);
        #pragma unroll
        for (int g = 0; g < 4; g++) ldm4(&bl[2*g][0], &sm[cur][3][br + g*16][bcl]);
        #pragma unroll
        for (int mt = 0; mt < 4; mt++)
            #pragma unroll
            for (int nt = 0; nt < 8; nt++)
                mma16816h(acc[mt][nt], ah[mt], bh[nt]);        // hi*hi
        #pragma unroll
        for (int mt = 0; mt < 4; mt++)
            #pragma unroll
            for (int nt = 0; nt < 8; nt++)
                mma16816h(acc[mt][nt], al[mt], bh[nt]);        // lo*hi
        #pragma unroll
        for (int mt = 0; mt < 4; mt++)
            #pragma unroll
            for (int nt = 0; nt < 8; nt++)
                mma16816h(acc[mt][nt], ah[mt], bl[nt]);        // hi*lo
        __syncthreads();
    }

    // epilogue: affine+relu + x + up, smem transpose, contiguous fuseT stores
    const int qr = lane >> 2, qc = (lane & 3) * 2;
    h16 (*trans)[136] = reinterpret_cast<h16 (*)[136]>(&sm[0][0][0][0]);  // [n_loc][c_loc]
    #pragma unroll
    for (int mt = 0; mt < 4; mt++)
        #pragma unroll
        for (int h = 0; h < 2; h++) {
            int crl = wm*64 + mt*16 + qr + 8*h;
            int row = row0 + crl;
            float sc = so[row], bi = bo[row];
            #pragma unroll
            for (int nt = 0; nt < 8; nt++) {
                int cl = wn*64 + nt*8 + qc;
                size_t xoff = ((size_t)b * CIN + row) * NPIX + n0 + cl;
                float2 xv = *reinterpret_cast<const float2*>(x + xoff);
                float2 uv = *reinterpret_cast<const float2*>(up + xoff);
                float v0 = fmaxf(fmaf(acc[mt][nt][2*h],   sc, bi), 0.f) + xv.x + uv.x;
                float v1 = fmaxf(fmaf(acc[mt][nt][2*h+1], sc, bi), 0.f) + xv.y + uv.y;
                trans[cl][crl]     = __float2half_rn(v0);
                trans[cl + 1][crl] = __float2half_rn(v1);
            }
        }
    __syncthreads();
    {
        int p = n0 + t;
        int y = p >> 6, xx = p & 63;
        h16* dst = g_fuseT + (((size_t)b*66 + y + 1)*66 + xx + 1)*512 + row0;
        uint4* d4 = reinterpret_cast<uint4*>(dst);
        const uint4* s4 = reinterpret_cast<const uint4*>(&trans[t][0]);
        #pragma unroll
        for (int g = 0; g < 16; g++) d4[g] = s4[g];
    }
}

// ================= launch =================
extern "C" void kernel_launch(void* const* d_in, const int* in_sizes, int n_in,
                              void* d_out, int out_size)
{
    const float* x  = (const float*)d_in[0];
    const float* up = (const float*)d_in[1];
    const float* wq = (const float*)d_in[2];
    const float* sq = (const float*)d_in[3];
    const float* bq = (const float*)d_in[4];
    const float* wk = (const float*)d_in[5];
    const float* sk = (const float*)d_in[6];
    const float* bk = (const float*)d_in[7];
    const float* wv = (const float*)d_in[8];
    const float* sv = (const float*)d_in[9];
    const float* bv = (const float*)d_in[10];
    const float* wo = (const float*)d_in[11];
    const float* so = (const float*)d_in[12];
    const float* bo = (const float*)d_in[13];
    const float* ws = (const float*)d_in[14];
    const float* ss = (const float*)d_in[15];
    const float* bs = (const float*)d_in[16];
    float* out = (float*)d_out;

    prep_split<<<16, 256>>>(wq, 64, 0);
    prep_split<<<16, 256>>>(wk, 64, 1);
    prep_split<<<128, 256>>>(wv, 512, 2);
    prep_wconv<<<288, 256>>>(ws);
    xt_kernel<<<dim3(64, 16, 8), 256>>>(x);
    mma_gemm<0><<<dim3(32, 1, 8), 128>>>(sq, bq, sk, bk, nullptr);
    mma_gemm<1><<<dim3(32, 4, 8), 128>>>(sv, bv, nullptr, nullptr, nullptr);
    sim_mma<<<dim3(4, 4, 8), 128>>>();
    sim_reduce<<<(BB * CIN * CKD + 255) / 256, 256>>>();
    wos_kernel<<<dim3(8, 8), 256>>>(wo);
    zero_borderT<<<(BB * 260 * 64 + 255) / 256, 256>>>();
    fuse_mma<<<dim3(32, 4, 8), 128>>>(x, up, so, bo);
    mma_gemm<2><<<dim3(32, 1, 8), 128>>>(ss, bs, nullptr, nullptr, out);
}

// round 10
// speedup vs baseline: 4.3802x; 1.4396x over previous
#include <cuda_runtime.h>
#include <cuda_fp16.h>
#include <math.h>

#define BB 8
#define CIN 512
#define NPIX 4096
#define CKD 64
#define COUT 128
#define KCONV 4608

typedef __half h16;

// ---------------- device scratch ----------------
__device__ __align__(16) h16 g_XT[(size_t)BB*NPIX*512];        // [b][n][c512] fp16
__device__ __align__(16) h16 g_fuseT[(size_t)BB*66*66*512];    // [b][y][x][c512] fp16
__device__ __align__(16) h16 g_Wqk[128*512];                   // hi only
__device__ __align__(16) h16 g_Wv[512*512];                    // hi only
__device__ __align__(16) h16 g_Wc[128*KCONV];                  // hi only, k'=(r9*512+ic)
__device__ __align__(16) h16 g_Vh[(size_t)BB*CIN*2*NPIX];      // [b][c][hi|lo][n]
__device__ __align__(16) h16 g_Kh[(size_t)BB*CKD*2*NPIX];      // [b][k][hi|lo][n]
__device__ __align__(16) h16 g_QT[(size_t)BB*NPIX*64];         // [b][n][hi64]
__device__ __align__(16) h16 g_WosH[BB*CIN*128];               // [b][o][hi64|lo64]
__device__ float g_simP[BB*4*CIN*CKD];
__device__ float g_simT[BB*CIN*CKD];

// ---------------- helpers ----------------
__device__ __forceinline__ unsigned pk2h(float a, float b) {
    __half2 h = __floats2half2_rn(a, b);
    return *reinterpret_cast<unsigned*>(&h);
}
__device__ __forceinline__ float hhi_f(float x) { return __half2float(__float2half_rn(x)); }
__device__ __forceinline__ void pack8h(const float* f, unsigned* hi) {
    #pragma unroll
    for (int i = 0; i < 4; i++) hi[i] = pk2h(f[2*i], f[2*i+1]);
}
__device__ __forceinline__ unsigned su32(const void* p) {
    return (unsigned)__cvta_generic_to_shared(p);
}
__device__ __forceinline__ void cpa16(void* sdst, const void* gsrc) {
    asm volatile("cp.async.cg.shared.global [%0], [%1], 16;" :: "r"(su32(sdst)), "l"(gsrc));
}
__device__ __forceinline__ void cp_commit() { asm volatile("cp.async.commit_group;" ::: "memory"); }
__device__ __forceinline__ void cp_wait1()  { asm volatile("cp.async.wait_group 1;" ::: "memory"); }
__device__ __forceinline__ void cp_wait0()  { asm volatile("cp.async.wait_group 0;" ::: "memory"); }
__device__ __forceinline__ void mma16816h(float* d, const unsigned* a, const unsigned* b) {
    asm("mma.sync.aligned.m16n8k16.row.col.f32.f16.f16.f32 "
        "{%0,%1,%2,%3},{%4,%5,%6,%7},{%8,%9},{%0,%1,%2,%3};"
        : "+f"(d[0]), "+f"(d[1]), "+f"(d[2]), "+f"(d[3])
        : "r"(a[0]), "r"(a[1]), "r"(a[2]), "r"(a[3]), "r"(b[0]), "r"(b[1]));
}
__device__ __forceinline__ void ldm4(unsigned* r, const h16* p) {
    asm volatile("ldmatrix.sync.aligned.m8n8.x4.shared.b16 {%0,%1,%2,%3}, [%4];"
        : "=r"(r[0]), "=r"(r[1]), "=r"(r[2]), "=r"(r[3]) : "r"(su32(p)));
}

// ---------------- prep: fp32 weights -> fp16 hi only ----------------
__global__ __launch_bounds__(256) void prep_split(const float* __restrict__ src,
                                                  int rows, int which)
{
    h16* dst = (which == 0) ? g_Wqk : (which == 1) ? (g_Wqk + 64*512) : g_Wv;
    int idx = blockIdx.x * 256 + threadIdx.x;
    if (idx >= rows * 64) return;
    int m = idx >> 6, kg = idx & 63;
    float f[8];
    *reinterpret_cast<float4*>(f)     = *reinterpret_cast<const float4*>(src + (size_t)m*512 + kg*8);
    *reinterpret_cast<float4*>(f + 4) = *reinterpret_cast<const float4*>(src + (size_t)m*512 + kg*8 + 4);
    unsigned hi[4];
    pack8h(f, hi);
    *reinterpret_cast<uint4*>(dst + (size_t)m * 512 + kg*8) = make_uint4(hi[0], hi[1], hi[2], hi[3]);
}

// ---------------- prep: conv weights permute -> fp16 hi only ----------------
__global__ __launch_bounds__(256) void prep_wconv(const float* __restrict__ ws)
{
    int idx = blockIdx.x * 256 + threadIdx.x;
    if (idx >= 128 * 576) return;
    int oc = idx / 576, kg = idx - oc * 576;
    int kp0 = kg * 8;
    int r9 = kp0 >> 9, ic = kp0 & 511;
    float f[8];
    #pragma unroll
    for (int j = 0; j < 8; j++)
        f[j] = ws[(size_t)oc * KCONV + (ic + j) * 9 + r9];
    unsigned hi[4];
    pack8h(f, hi);
    *reinterpret_cast<uint4*>(g_Wc + (size_t)oc * KCONV + kp0) = make_uint4(hi[0], hi[1], hi[2], hi[3]);
}

// ---------------- xt: x[b][c][n] -> XT[b][n][c] fp16 ----------------
__global__ __launch_bounds__(256) void xt_kernel(const float* __restrict__ x)
{
    __shared__ float tile[32][65];
    const int b = blockIdx.z, c0 = blockIdx.y * 32, n0 = blockIdx.x * 64;
    const int t = threadIdx.x;
    {
        int r = t >> 3, nq = (t & 7) * 8;
        const float* src = x + ((size_t)b * CIN + c0 + r) * NPIX + n0 + nq;
        float4 a = *reinterpret_cast<const float4*>(src);
        float4 c = *reinterpret_cast<const float4*>(src + 4);
        tile[r][nq+0]=a.x; tile[r][nq+1]=a.y; tile[r][nq+2]=a.z; tile[r][nq+3]=a.w;
        tile[r][nq+4]=c.x; tile[r][nq+5]=c.y; tile[r][nq+6]=c.z; tile[r][nq+7]=c.w;
    }
    __syncthreads();
    {
        int xc = t & 63, grp = t >> 6;
        float f[8];
        #pragma unroll
        for (int i = 0; i < 8; i++) f[i] = tile[grp*8 + i][xc];
        unsigned hh[4];
        pack8h(f, hh);
        h16* d = g_XT + ((size_t)b * NPIX + n0 + xc) * 512 + c0 + grp*8;
        *reinterpret_cast<uint4*>(d) = make_uint4(hh[0], hh[1], hh[2], hh[3]);
    }
}

// ---------------- big GEMMs: 1-pass fp16, ldmatrix, 64x64 warp tiles ----------------
// CTA 128x128, 4 warps. Tiles per stage: [0]=A [1]=B.
template<int MODE>
__global__ __launch_bounds__(128) void mma_gemm(
    const float* __restrict__ s0, const float* __restrict__ b0v,
    const float* __restrict__ s1, const float* __restrict__ b1v,
    float* __restrict__ outp)
{
    constexpr int KD = (MODE == 2) ? KCONV : 512;
    constexpr int NSTEP = KD / 16;
    __shared__ __align__(16) h16 sm[2][2][128][24];   // 24KB
    const int bidx = blockIdx.z;
    const int n0 = blockIdx.x * 128;
    const int row0 = blockIdx.y * 128;
    const int t = threadIdx.x;
    const int lane = t & 31, w = t >> 5, wm = w >> 1, wn = w & 1;

    float acc[4][8][4];
    #pragma unroll
    for (int i = 0; i < 4; i++)
        #pragma unroll
        for (int j = 0; j < 8; j++)
            #pragma unroll
            for (int c = 0; c < 4; c++) acc[i][j][c] = 0.f;

    const h16* W = (MODE == 0) ? g_Wqk : (MODE == 1) ? g_Wv : g_Wc;
    const h16* aSrc = W + (size_t)(row0 + t) * KD;
    const h16* bSrcX = g_XT + ((size_t)bidx * NPIX + n0 + t) * 512;
    int yi = 0, xi = 0;
    if (MODE == 2) { int p = n0 + t; yi = p >> 6; xi = p & 63; }

    auto load = [&](int st, int kc) {
        cpa16(&sm[st][0][t][0], aSrc + kc);
        cpa16(&sm[st][0][t][8], aSrc + kc + 8);
        const h16* bp;
        if (MODE == 2) {
            int r9 = kc >> 9, kin = kc & 511;
            int dy = r9 / 3, dx = r9 - dy*3;
            bp = g_fuseT + (((size_t)bidx*66 + yi + dy)*66 + xi + dx)*512 + kin;
        } else {
            bp = bSrcX + kc;
        }
        cpa16(&sm[st][1][t][0], bp);
        cpa16(&sm[st][1][t][8], bp + 8);
        cp_commit();
    };

    const int ar  = wm*64 + (lane & 15);
    const int acl = (lane >> 4) * 8;
    const int br  = wn*64 + ((lane >> 4) << 3) + (lane & 7);
    const int bcl = ((lane >> 3) & 1) * 8;

    load(0, 0);
    #pragma unroll 1
    for (int kt = 0; kt < NSTEP; kt++) {
        int cur = kt & 1;
        if (kt + 1 < NSTEP) { load(cur ^ 1, (kt+1)*16); cp_wait1(); }
        else                 cp_wait0();
        __syncthreads();

        unsigned ah[4][4], bfr[8][2];
        #pragma unroll
        for (int mt = 0; mt < 4; mt++) ldm4(ah[mt], &sm[cur][0][ar + mt*16][acl]);
        #pragma unroll
        for (int g = 0; g < 4; g++) ldm4(&bfr[2*g][0], &sm[cur][1][br + g*16][bcl]);
        #pragma unroll
        for (int mt = 0; mt < 4; mt++)
            #pragma unroll
            for (int nt = 0; nt < 8; nt++)
                mma16816h(acc[mt][nt], ah[mt], bfr[nt]);
        __syncthreads();
    }

    const int qr = lane >> 2, qc = (lane & 3) * 2;

    if (MODE == 0) {
        #pragma unroll
        for (int mt = 0; mt < 4; mt++)
            #pragma unroll
            for (int h = 0; h < 2; h++) {
                int ri = (mt*16 + qr + 8*h) & 63;
                float sc = wm ? s1[ri] : s0[ri];
                float bi = wm ? b1v[ri] : b0v[ri];
                #pragma unroll
                for (int nt = 0; nt < 8; nt++) {
                    acc[mt][nt][2*h]   = fmaf(acc[mt][nt][2*h],   sc, bi);
                    acc[mt][nt][2*h+1] = fmaf(acc[mt][nt][2*h+1], sc, bi);
                }
            }
        float inv[8][2];
        #pragma unroll
        for (int nt = 0; nt < 8; nt++)
            #pragma unroll
            for (int j = 0; j < 2; j++) {
                float ss = 0.f;
                #pragma unroll
                for (int mt = 0; mt < 4; mt++)
                    ss += acc[mt][nt][j]*acc[mt][nt][j] + acc[mt][nt][2+j]*acc[mt][nt][2+j];
                ss += __shfl_xor_sync(0xffffffffu, ss, 4);
                ss += __shfl_xor_sync(0xffffffffu, ss, 8);
                ss += __shfl_xor_sync(0xffffffffu, ss, 16);
                inv[nt][j] = 1.f / fmaxf(sqrtf(ss), 1e-12f);
            }
        if (wm == 0) {
            // Q rows: pixel-major fp16 hi only
            h16* qd = g_QT + (size_t)bidx * NPIX * 64;
            #pragma unroll
            for (int mt = 0; mt < 4; mt++)
                #pragma unroll
                for (int h = 0; h < 2; h++) {
                    int ch = (mt*16 + qr + 8*h) & 63;
                    #pragma unroll
                    for (int nt = 0; nt < 8; nt++) {
                        int col = n0 + wn*64 + nt*8 + qc;
                        qd[(size_t)col*64 + ch]     = __float2half_rn(acc[mt][nt][2*h]   * inv[nt][0]);
                        qd[(size_t)(col+1)*64 + ch] = __float2half_rn(acc[mt][nt][2*h+1] * inv[nt][1]);
                    }
                }
        } else {
            // K rows: split fp16 hi/lo for sim_mma
            #pragma unroll
            for (int mt = 0; mt < 4; mt++)
                #pragma unroll
                for (int h = 0; h < 2; h++) {
                    int ch = (mt*16 + qr + 8*h) & 63;
                    h16* kd = g_Kh + ((size_t)bidx * CKD + ch) * 2 * NPIX;
                    #pragma unroll
                    for (int nt = 0; nt < 8; nt++) {
                        int col = n0 + wn*64 + nt*8 + qc;
                        float v0 = acc[mt][nt][2*h]   * inv[nt][0];
                        float v1 = acc[mt][nt][2*h+1] * inv[nt][1];
                        *reinterpret_cast<unsigned*>(&kd[col]) = pk2h(v0, v1);
                        *reinterpret_cast<unsigned*>(&kd[NPIX + col]) =
                            pk2h(v0 - hhi_f(v0), v1 - hhi_f(v1));
                    }
                }
        }
    } else if (MODE == 1) {
        #pragma unroll
        for (int mt = 0; mt < 4; mt++)
            #pragma unroll
            for (int h = 0; h < 2; h++) {
                int row = row0 + wm*64 + mt*16 + qr + 8*h;
                float sc = s0[row], bi = b0v[row];
                h16* vd = g_Vh + ((size_t)bidx * CIN + row) * 2 * NPIX;
                #pragma unroll
                for (int nt = 0; nt < 8; nt++) {
                    int col = n0 + wn*64 + nt*8 + qc;
                    float v0 = fmaxf(fmaf(acc[mt][nt][2*h],   sc, bi), 0.f);
                    float v1 = fmaxf(fmaf(acc[mt][nt][2*h+1], sc, bi), 0.f);
                    *reinterpret_cast<unsigned*>(&vd[col]) = pk2h(v0, v1);
                    *reinterpret_cast<unsigned*>(&vd[NPIX + col]) =
                        pk2h(v0 - hhi_f(v0), v1 - hhi_f(v1));
                }
            }
    } else {
        #pragma unroll
        for (int mt = 0; mt < 4; mt++)
            #pragma unroll
            for (int h = 0; h < 2; h++) {
                int row = row0 + wm*64 + mt*16 + qr + 8*h;
                float sc = s0[row], bi = b0v[row];
                #pragma unroll
                for (int nt = 0; nt < 8; nt++) {
                    int col = n0 + wn*64 + nt*8 + qc;
                    float2 o;
                    o.x = fmaxf(fmaf(acc[mt][nt][2*h],   sc, bi), 0.f);
                    o.y = fmaxf(fmaf(acc[mt][nt][2*h+1], sc, bi), 0.f);
                    *reinterpret_cast<float2*>(
                        &outp[((size_t)bidx * COUT + row) * NPIX + col]) = o;
                }
            }
    }
}

// ---------------- sim via mma: 3-pass on split V/K ----------------
__global__ __launch_bounds__(128) void sim_mma()
{
    __shared__ __align__(16) h16 sm[2][4][128][24];   // 48KB
    const int b = blockIdx.z, chunk = blockIdx.y, c0 = blockIdx.x * 128;
    const int t = threadIdx.x;
    const int lane = t & 31, w = t >> 5, wm = w >> 1, wn = w & 1;

    float acc[4][4][4];
    #pragma unroll
    for (int i = 0; i < 4; i++)
        #pragma unroll
        for (int j = 0; j < 4; j++)
            #pragma unroll
            for (int c = 0; c < 4; c++) acc[i][j][c] = 0.f;

    const h16* aSrc = g_Vh + ((size_t)b * CIN + c0 + t) * 2 * NPIX + chunk * 1024;
    const h16* bSrc = g_Kh + ((size_t)b * CKD + (t & 63)) * 2 * NPIX + chunk * 1024;

    auto load = [&](int st, int kc) {
        cpa16(&sm[st][0][t][0], aSrc + kc);
        cpa16(&sm[st][0][t][8], aSrc + kc + 8);
        cpa16(&sm[st][1][t][0], aSrc + NPIX + kc);
        cpa16(&sm[st][1][t][8], aSrc + NPIX + kc + 8);
        if (t < 64) {
            cpa16(&sm[st][2][t][0], bSrc + kc);
            cpa16(&sm[st][2][t][8], bSrc + kc + 8);
            cpa16(&sm[st][3][t][0], bSrc + NPIX + kc);
            cpa16(&sm[st][3][t][8], bSrc + NPIX + kc + 8);
        }
        cp_commit();
    };

    const int ar  = wm*64 + (lane & 15);
    const int acl = (lane >> 4) * 8;
    const int br  = wn*32 + ((lane >> 4) << 3) + (lane & 7);
    const int bcl = ((lane >> 3) & 1) * 8;

    load(0, 0);
    #pragma unroll 1
    for (int kt = 0; kt < 64; kt++) {
        int cur = kt & 1;
        if (kt + 1 < 64) { load(cur ^ 1, (kt+1)*16); cp_wait1(); }
        else              cp_wait0();
        __syncthreads();

        unsigned ah[4][4], al[4][4], bh[4][2], bl[4][2];
        #pragma unroll
        for (int mt = 0; mt < 4; mt++) ldm4(ah[mt], &sm[cur][0][ar + mt*16][acl]);
        #pragma unroll
        for (int mt = 0; mt < 4; mt++) ldm4(al[mt], &sm[cur][1][ar + mt*16][acl]);
        #pragma unroll
        for (int g = 0; g < 2; g++) ldm4(&bh[2*g][0], &sm[cur][2][br + g*16][bcl]);
        #pragma unroll
        for (int g = 0; g < 2; g++) ldm4(&bl[2*g][0], &sm[cur][3][br + g*16][bcl]);
        #pragma unroll
        for (int mt = 0; mt < 4; mt++)
            #pragma unroll
            for (int nt = 0; nt < 4; nt++)
                mma16816h(acc[mt][nt], ah[mt], bh[nt]);
        #pragma unroll
        for (int mt = 0; mt < 4; mt++)
            #pragma unroll
            for (int nt = 0; nt < 4; nt++)
                mma16816h(acc[mt][nt], al[mt], bh[nt]);
        #pragma unroll
        for (int mt = 0; mt < 4; mt++)
            #pragma unroll
            for (int nt = 0; nt < 4; nt++)
                mma16816h(acc[mt][nt], ah[mt], bl[nt]);
        __syncthreads();
    }

    const int qr = lane >> 2, qc = (lane & 3) * 2;
    float* pb = g_simP + (size_t)(b*4 + chunk) * CIN * CKD;
    #pragma unroll
    for (int mt = 0; mt < 4; mt++)
        #pragma unroll
        for (int h = 0; h < 2; h++) {
            int row = c0 + wm*64 + mt*16 + qr + 8*h;
            #pragma unroll
            for (int nt = 0; nt < 4; nt++) {
                int col = wn*32 + nt*8 + qc;
                float2 o = make_float2(acc[mt][nt][2*h], acc[mt][nt][2*h+1]);
                *reinterpret_cast<float2*>(&pb[(size_t)row * CKD + col]) = o;
            }
        }
}

__global__ __launch_bounds__(256) void sim_reduce()
{
    int idx = blockIdx.x * 256 + threadIdx.x;
    if (idx >= BB * CIN * CKD) return;
    int b = idx / (CIN * CKD);
    int rem = idx - b * CIN * CKD;
    float s = 0.f;
    #pragma unroll
    for (int p = 0; p < 4; p++)
        s += g_simP[(size_t)(b*4 + p) * CIN * CKD + rem];
    g_simT[idx] = s;
}

// ---------------- wos: Wo @ simT -> split fp16 [b][o][hi64|lo64] ----------------
__global__ __launch_bounds__(256) void wos_kernel(const float* __restrict__ wo)
{
    __shared__ __align__(16) float As[16][64];
    __shared__ __align__(16) float Bs[16][64];
    const int b = blockIdx.y;
    const int row0 = blockIdx.x * 64;
    const float* ST = g_simT + (size_t)b * CIN * CKD;
    const int t = threadIdx.x;
    const int tr = t >> 4, tc = t & 15;
    float acc[4][4];
    #pragma unroll
    for (int i = 0; i < 4; i++)
        #pragma unroll
        for (int j = 0; j < 4; j++) acc[i][j] = 0.f;

    for (int kb = 0; kb < CIN; kb += 16) {
        {
            int r  = t >> 2;
            int k4 = (t & 3) << 2;
            float4 va = *reinterpret_cast<const float4*>(wo + (size_t)(row0 + r) * CIN + kb + k4);
            As[k4+0][r] = va.x; As[k4+1][r] = va.y; As[k4+2][r] = va.z; As[k4+3][r] = va.w;
            int kk = t >> 4;
            int n4 = (t & 15) << 2;
            *reinterpret_cast<float4*>(&Bs[kk][n4]) =
                *reinterpret_cast<const float4*>(ST + (size_t)(kb + kk) * CKD + n4);
        }
        __syncthreads();
        #pragma unroll
        for (int kk = 0; kk < 16; kk++) {
            float4 a = *reinterpret_cast<float4*>(&As[kk][tr*4]);
            float4 bbv = *reinterpret_cast<float4*>(&Bs[kk][tc*4]);
            float av[4] = {a.x,a.y,a.z,a.w};
            float bv[4] = {bbv.x,bbv.y,bbv.z,bbv.w};
            #pragma unroll
            for (int i = 0; i < 4; i++)
                #pragma unroll
                for (int j = 0; j < 4; j++)
                    acc[i][j] = fmaf(av[i], bv[j], acc[i][j]);
        }
        __syncthreads();
    }
    #pragma unroll
    for (int i = 0; i < 4; i++) {
        int o = row0 + tr * 4 + i;
        float v0 = acc[i][0], v1 = acc[i][1], v2 = acc[i][2], v3 = acc[i][3];
        h16* d = g_WosH + ((size_t)b * CIN + o) * 128 + tc*4;
        *reinterpret_cast<uint2*>(d) =
            make_uint2(pk2h(v0, v1), pk2h(v2, v3));
        *reinterpret_cast<uint2*>(d + 64) =
            make_uint2(pk2h(v0 - hhi_f(v0), v1 - hhi_f(v1)),
                       pk2h(v2 - hhi_f(v2), v3 - hhi_f(v3)));
    }
}

// ---------------- zero fuseT borders ----------------
__global__ __launch_bounds__(256) void zero_borderT()
{
    int idx = blockIdx.x * 256 + threadIdx.x;
    if (idx >= BB * 260 * 64) return;
    int c16 = idx & 63;
    int r = idx >> 6;
    int b = r / 260, p = r - b * 260;
    int y, x;
    if (p < 66)       { y = 0;  x = p; }
    else if (p < 132) { y = 65; x = p - 66; }
    else if (p < 196) { y = p - 132 + 1; x = 0; }
    else              { y = p - 196 + 1; x = 65; }
    uint4* d = reinterpret_cast<uint4*>(g_fuseT + (((size_t)b*66 + y)*66 + x)*512);
    d[c16] = make_uint4(0, 0, 0, 0);
}

// ---------------- fuse via mma: 2-pass (Wos hi+lo, Q hi) ----------------
__global__ __launch_bounds__(128) void fuse_mma(
    const float* __restrict__ x, const float* __restrict__ up,
    const float* __restrict__ so, const float* __restrict__ bo)
{
    __shared__ __align__(16) h16 sm[2][3][128][24];   // 36KB; reused as transpose buf
    const int b = blockIdx.z;
    const int n0 = blockIdx.x * 128;
    const int row0 = blockIdx.y * 128;
    const int t = threadIdx.x;
    const int lane = t & 31, w = t >> 5, wm = w >> 1, wn = w & 1;

    float acc[4][8][4];
    #pragma unroll
    for (int i = 0; i < 4; i++)
        #pragma unroll
        for (int j = 0; j < 8; j++)
            #pragma unroll
            for (int c = 0; c < 4; c++) acc[i][j][c] = 0.f;

    const h16* aSrc = g_WosH + ((size_t)b * CIN + row0 + t) * 128;
    const h16* bSrc = g_QT   + ((size_t)b * NPIX + n0 + t) * 64;

    auto load = [&](int st, int kc) {
        cpa16(&sm[st][0][t][0], aSrc + kc);
        cpa16(&sm[st][0][t][8], aSrc + kc + 8);
        cpa16(&sm[st][1][t][0], aSrc + 64 + kc);
        cpa16(&sm[st][1][t][8], aSrc + 64 + kc + 8);
        cpa16(&sm[st][2][t][0], bSrc + kc);
        cpa16(&sm[st][2][t][8], bSrc + kc + 8);
        cp_commit();
    };

    const int ar  = wm*64 + (lane & 15);
    const int acl = (lane >> 4) * 8;
    const int br  = wn*64 + ((lane >> 4) << 3) + (lane & 7);
    const int bcl = ((lane >> 3) & 1) * 8;

    load(0, 0);
    #pragma unroll 1
    for (int kt = 0; kt < 4; kt++) {
        int cur = kt & 1;
        if (kt + 1 < 4) { load(cur ^ 1, (kt+1)*16); cp_wait1(); }
        else             cp_wait0();
        __syncthreads();

        unsigned ah[4][4], al[4][4], bh[8][2];
        #pragma unroll
        for (int mt = 0; mt < 4; mt++) ldm4(ah[mt], &sm[cur][0][ar + mt*16][acl]);
        #pragma unroll
        for (int mt = 0; mt < 4; mt++) ldm4(al[mt], &sm[cur][1][ar + mt*16][acl]);
        #pragma unroll
        for (int g = 0; g < 4; g++) ldm4(&bh[2*g][0], &sm[cur][2][br + g*16][bcl]);
        #pragma unroll
        for (int mt = 0; mt < 4; mt++)
            #pragma unroll
            for (int nt = 0; nt < 8; nt++)
                mma16816h(acc[mt][nt], ah[mt], bh[nt]);        // hi*hi
        #pragma unroll
        for (int mt = 0; mt < 4; mt++)
            #pragma unroll
            for (int nt = 0; nt < 8; nt++)
                mma16816h(acc[mt][nt], al[mt], bh[nt]);        // lo*hi
        __syncthreads();
    }

    // epilogue: affine+relu + x + up, smem transpose, contiguous fuseT stores
    const int qr = lane >> 2, qc = (lane & 3) * 2;
    h16 (*trans)[136] = reinterpret_cast<h16 (*)[136]>(&sm[0][0][0][0]);  // [n_loc][c_loc] 34.8KB
    #pragma unroll
    for (int mt = 0; mt < 4; mt++)
        #pragma unroll
        for (int h = 0; h < 2; h++) {
            int crl = wm*64 + mt*16 + qr + 8*h;
            int row = row0 + crl;
            float sc = so[row], bi = bo[row];
            #pragma unroll
            for (int nt = 0; nt < 8; nt++) {
                int cl = wn*64 + nt*8 + qc;
                size_t xoff = ((size_t)b * CIN + row) * NPIX + n0 + cl;
                float2 xv = *reinterpret_cast<const float2*>(x + xoff);
                float2 uv = *reinterpret_cast<const float2*>(up + xoff);
                float v0 = fmaxf(fmaf(acc[mt][nt][2*h],   sc, bi), 0.f) + xv.x + uv.x;
                float v1 = fmaxf(fmaf(acc[mt][nt][2*h+1], sc, bi), 0.f) + xv.y + uv.y;
                trans[cl][crl]     = __float2half_rn(v0);
                trans[cl + 1][crl] = __float2half_rn(v1);
            }
        }
    __syncthreads();
    {
        int p = n0 + t;
        int y = p >> 6, xx = p & 63;
        h16* dst = g_fuseT + (((size_t)b*66 + y + 1)*66 + xx + 1)*512 + row0;
        uint4* d4 = reinterpret_cast<uint4*>(dst);
        const uint4* s4 = reinterpret_cast<const uint4*>(&trans[t][0]);
        #pragma unroll
        for (int g = 0; g < 16; g++) d4[g] = s4[g];
    }
}

// ================= launch =================
extern "C" void kernel_launch(void* const* d_in, const int* in_sizes, int n_in,
                              void* d_out, int out_size)
{
    const float* x  = (const float*)d_in[0];
    const float* up = (const float*)d_in[1];
    const float* wq = (const float*)d_in[2];
    const float* sq = (const float*)d_in[3];
    const float* bq = (const float*)d_in[4];
    const float* wk = (const float*)d_in[5];
    const float* sk = (const float*)d_in[6];
    const float* bk = (const float*)d_in[7];
    const float* wv = (const float*)d_in[8];
    const float* sv = (const float*)d_in[9];
    const float* bv = (const float*)d_in[10];
    const float* wo = (const float*)d_in[11];
    const float* so = (const float*)d_in[12];
    const float* bo = (const float*)d_in[13];
    const float* ws = (const float*)d_in[14];
    const float* ss = (const float*)d_in[15];
    const float* bs = (const float*)d_in[16];
    float* out = (float*)d_out;

    prep_split<<<16, 256>>>(wq, 64, 0);
    prep_split<<<16, 256>>>(wk, 64, 1);
    prep_split<<<128, 256>>>(wv, 512, 2);
    prep_wconv<<<288, 256>>>(ws);
    xt_kernel<<<dim3(64, 16, 8), 256>>>(x);
    mma_gemm<0><<<dim3(32, 1, 8), 128>>>(sq, bq, sk, bk, nullptr);
    mma_gemm<1><<<dim3(32, 4, 8), 128>>>(sv, bv, nullptr, nullptr, nullptr);
    sim_mma<<<dim3(4, 4, 8), 128>>>();
    sim_reduce<<<(BB * CIN * CKD + 255) / 256, 256>>>();
    wos_kernel<<<dim3(8, 8), 256>>>(wo);
    zero_borderT<<<(BB * 260 * 64 + 255) / 256, 256>>>();
    fuse_mma<<<dim3(32, 4, 8), 128>>>(x, up, so, bo);
    mma_gemm<2><<<dim3(32, 1, 8), 128>>>(ss, bs, nullptr, nullptr, out);
}